// round 4
// baseline (speedup 1.0000x reference)
#include <cuda_runtime.h>
#include <cuda_bf16.h>
#include <cstdint>

// ---------------------------------------------------------------------------
// PoolOnlyGNN — mma.sync bf16x3 persistent version (no 'a'-gated instructions).
// ---------------------------------------------------------------------------

#define MAXG  8192
#define NSLOT 4

__device__ float g_U[3 * MAXG * 128];
__device__ float g_Dn[3 * MAXG];
__device__ int g_is64;
__device__ unsigned short g_Wsw[6 * 16384];  // (Wh,Wl) x 3 steps, ldmatrix layout
__device__ float g_xgA[MAXG * 128];
__device__ float g_xgB[MAXG * 128];

__device__ __forceinline__ uint32_t smem_u32(const void* p) {
    uint32_t a;
    asm("{ .reg .u64 t; cvta.to.shared.u64 t, %1; cvt.u32.u64 %0, t; }"
        : "=r"(a) : "l"(p));
    return a;
}
__device__ __forceinline__ void ldsm4(uint32_t* r, uint32_t a) {
    asm volatile("ldmatrix.sync.aligned.m8n8.x4.shared.b16 {%0,%1,%2,%3}, [%4];"
                 : "=r"(r[0]), "=r"(r[1]), "=r"(r[2]), "=r"(r[3]) : "r"(a));
}
__device__ __forceinline__ void mma16816(float* c, const uint32_t* a,
                                         uint32_t b0, uint32_t b1) {
    asm volatile(
        "mma.sync.aligned.m16n8k16.row.col.f32.bf16.bf16.f32 "
        "{%0,%1,%2,%3}, {%4,%5,%6,%7}, {%8,%9}, {%0,%1,%2,%3};"
        : "+f"(c[0]), "+f"(c[1]), "+f"(c[2]), "+f"(c[3])
        : "r"(a[0]), "r"(a[1]), "r"(a[2]), "r"(a[3]), "r"(b0), "r"(b1));
}
__device__ __forceinline__ float leaky1(float v) { return v >= 0.f ? v : 0.01f * v; }

// image byte offset for element (row n, col k) in a 128x128 bf16 ldmatrix tile:
// 256B per row, 16B chunks xor-swizzled by row&7 (conflict-free STS + LDSM).
__device__ __forceinline__ int img_off(int n, int k) {
    return n * 256 + (((k >> 3) ^ (n & 7)) << 4) + (k & 7) * 2;
}

__global__ void init_kernel(const int* __restrict__ bptr,
                            const float* __restrict__ feat_w, int N, int G) {
    int tid = blockIdx.x * blockDim.x + threadIdx.x;
    int stride = gridDim.x * blockDim.x;
    for (int i = tid; i < 3 * G * 128; i += stride) g_U[i] = 0.f;
    for (int i = tid; i < 3 * G; i += stride) g_Dn[i] = 0.f;
    // Build hi/lo bf16 images of feat_w: image row = output col n, k along row.
    for (int i = tid; i < 3 * 16384; i += stride) {
        int s = i >> 14, r = i & 16383;
        int k = r >> 7, n = r & 127;           // feat_w[s][k][n]
        float wv = feat_w[i];
        __nv_bfloat16 bh = __float2bfloat16(wv);
        __nv_bfloat16 bl = __float2bfloat16(wv - __bfloat162float(bh));
        int off = img_off(n, k) >> 1;
        g_Wsw[(2 * s) * 16384 + off] = *(const unsigned short*)&bh;
        g_Wsw[(2 * s + 1) * 16384 + off] = *(const unsigned short*)&bl;
    }
    if (tid == 0) {
        int probe = (N & 1) ? (N - 2) : (N - 1);
        if (probe < 0) probe = 0;
        g_is64 = (bptr[probe] == 0) ? 1 : 0;
    }
}

// smem byte offsets
#define OFF_W     0         // 196608 : 6 W images
#define OFF_XHI   196608    // 8192   : x hi tile (32 rows x 256B)
#define OFF_XLO   204800    // 8192
#define OFF_SLOT  212992    // 6144   : 3 steps x NSLOT x 128 f32
#define OFF_AD    219136    // 48     : 3 x NSLOT denom slots
#define OFF_ES    219184    // 384    : e[3][32]
#define OFF_BS    219568    // 128    : batch id per row
#define OFF_GW    219696    // 1536   : gate_w
#define OFF_FB    221232    // 1536   : feat_b
#define SMEM_BYTES 222768

__global__ void __launch_bounds__(256, 1) fused_pool(
    const float* __restrict__ x, const int* __restrict__ bptr,
    const float* __restrict__ gate_w, const float* __restrict__ gate_b,
    const float* __restrict__ feat_b, float* __restrict__ x_out,
    int N, int G, int ntiles) {
    extern __shared__ char sm[];
    float* slots = (float*)(sm + OFF_SLOT);
    float* aD = (float*)(sm + OFF_AD);
    float* eS = (float*)(sm + OFF_ES);
    int* bS = (int*)(sm + OFF_BS);
    float* gws = (float*)(sm + OFF_GW);
    float* fbs = (float*)(sm + OFF_FB);
    const uint32_t sb = smem_u32(sm);
    const uint32_t xhiB = sb + OFF_XHI, xloB = sb + OFF_XLO;

    const int t = threadIdx.x, lane = t & 31, w = t >> 5;

    {  // stage the six 32KB W images once
        const int4* srcw = (const int4*)g_Wsw;
        int4* dstw = (int4*)sm;
        for (int i = t; i < 12288; i += 256) dstw[i] = srcw[i];
    }
    for (int i = t; i < 384; i += 256) { gws[i] = gate_w[i]; fbs[i] = feat_b[i]; }
    for (int i = t; i < 3 * NSLOT * 128; i += 256) slots[i] = 0.f;
    if (t < 3 * NSLOT) aD[t] = 0.f;
    __syncthreads();

    const int strb = g_is64 ? 2 : 1;
    const float gb0 = gate_b[0], gb1 = gate_b[1], gb2 = gate_b[2];
    const int r = t >> 3, p = t & 7;  // loader coords: row 0..31, 16-col part
    const int n0 = w * 16;            // this warp's output-col slice

    for (int tile = blockIdx.x; tile < ntiles; tile += gridDim.x) {
        const long long row0 = (long long)tile * 32;
        const long long grow = row0 + r;
        const bool ok = grow < (long long)N;
        const long long crow = ok ? grow : (long long)N - 1;

        // ---- load x (32 rows), gates, bf16 split -> smem, copy x->out
        const float4* xr = ((const float4*)x) + crow * 32;
        float4 f[4];
        float p0 = 0.f, p1 = 0.f, p2 = 0.f;
#pragma unroll
        for (int j = 0; j < 4; j++) {
            f[j] = ok ? __ldg(xr + p * 4 + j)
                      : make_float4(0.f, 0.f, 0.f, 0.f);
            const float* gv = &gws[p * 16 + j * 4];
            p0 += f[j].x * gv[0] + f[j].y * gv[1] + f[j].z * gv[2] + f[j].w * gv[3];
            gv += 128;
            p1 += f[j].x * gv[0] + f[j].y * gv[1] + f[j].z * gv[2] + f[j].w * gv[3];
            gv += 128;
            p2 += f[j].x * gv[0] + f[j].y * gv[1] + f[j].z * gv[2] + f[j].w * gv[3];
        }
#pragma unroll
        for (int o = 4; o > 0; o >>= 1) {
            p0 += __shfl_down_sync(0xffffffffu, p0, o, 8);
            p1 += __shfl_down_sync(0xffffffffu, p1, o, 8);
            p2 += __shfl_down_sync(0xffffffffu, p2, o, 8);
        }
        if (p == 0) {
            eS[0 * 32 + r] = ok ? expf(p0 + gb0) : 0.f;
            eS[1 * 32 + r] = ok ? expf(p1 + gb1) : 0.f;
            eS[2 * 32 + r] = ok ? expf(p2 + gb2) : 0.f;
            bS[r] = bptr[crow * strb];
        }
#pragma unroll
        for (int j = 0; j < 4; j++) {
            __nv_bfloat162 ha = __floats2bfloat162_rn(f[j].x, f[j].y);
            __nv_bfloat162 hb = __floats2bfloat162_rn(f[j].z, f[j].w);
            float2 fa = __bfloat1622float2(ha), fb2 = __bfloat1622float2(hb);
            __nv_bfloat162 la = __floats2bfloat162_rn(f[j].x - fa.x, f[j].y - fa.y);
            __nv_bfloat162 lb = __floats2bfloat162_rn(f[j].z - fb2.x, f[j].w - fb2.y);
            int chunk = 2 * p + (j >> 1);
            int off = r * 256 + ((chunk ^ (r & 7)) << 4) + (j & 1) * 8;
            *(uint2*)(sm + OFF_XHI + off) =
                make_uint2(*(uint32_t*)&ha, *(uint32_t*)&hb);
            *(uint2*)(sm + OFF_XLO + off) =
                make_uint2(*(uint32_t*)&la, *(uint32_t*)&lb);
            if (ok && x_out) ((float4*)x_out)[grow * 32 + p * 4 + j] = f[j];
        }
        __syncthreads();
        const int b0 = bS[0];

        // ---- GEMM: warp covers 32 rows x 16 cols, 3 steps, bf16x3
        float C[3][2][2][4];
#pragma unroll
        for (int s = 0; s < 3; s++)
#pragma unroll
            for (int mb = 0; mb < 2; mb++)
#pragma unroll
                for (int nf = 0; nf < 2; nf++)
#pragma unroll
                    for (int q = 0; q < 4; q++) C[s][mb][nf][q] = 0.f;

        const int arow_l = lane & 15, a_kodd = lane >> 4;
        const int brow = n0 + (lane & 7) + ((lane >> 4) << 3);
        const int b_kodd = (lane >> 3) & 1;
#pragma unroll
        for (int kb = 0; kb < 8; kb++) {
            uint32_t Ah[2][4], Al[2][4];
#pragma unroll
            for (int mb = 0; mb < 2; mb++) {
                int arow = mb * 16 + arow_l;
                int achunk = 2 * kb + a_kodd;
                uint32_t aoff = arow * 256 + ((achunk ^ (arow & 7)) << 4);
                ldsm4(Ah[mb], xhiB + aoff);
                ldsm4(Al[mb], xloB + aoff);
            }
            int bchunk = 2 * kb + b_kodd;
            uint32_t boff = brow * 256 + ((bchunk ^ (brow & 7)) << 4);
#pragma unroll
            for (int s = 0; s < 3; s++) {
                uint32_t Bh[4], Bl[4];
                ldsm4(Bh, sb + (2 * s) * 32768 + boff);
                ldsm4(Bl, sb + (2 * s + 1) * 32768 + boff);
#pragma unroll
                for (int mb = 0; mb < 2; mb++)
#pragma unroll
                    for (int nf = 0; nf < 2; nf++) {
                        mma16816(C[s][mb][nf], Ah[mb], Bh[2 * nf], Bh[2 * nf + 1]);
                        mma16816(C[s][mb][nf], Al[mb], Bh[2 * nf], Bh[2 * nf + 1]);
                        mma16816(C[s][mb][nf], Ah[mb], Bl[2 * nf], Bl[2 * nf + 1]);
                    }
            }
        }

        // ---- epilogue: bias + leaky + e-weight -> slot atomics
        const int g = lane >> 2, tq = lane & 3;
#pragma unroll
        for (int s = 0; s < 3; s++)
#pragma unroll
            for (int mb = 0; mb < 2; mb++)
#pragma unroll
                for (int nf = 0; nf < 2; nf++) {
                    int col = n0 + nf * 8 + tq * 2;
                    float bi0 = fbs[s * 128 + col], bi1 = fbs[s * 128 + col + 1];
                    int r0 = mb * 16 + g, r1 = r0 + 8;
                    float e0 = eS[s * 32 + r0], e1 = eS[s * 32 + r1];
                    float v00 = leaky1(C[s][mb][nf][0] + bi0) * e0;
                    float v01 = leaky1(C[s][mb][nf][1] + bi1) * e0;
                    float v10 = leaky1(C[s][mb][nf][2] + bi0) * e1;
                    float v11 = leaky1(C[s][mb][nf][3] + bi1) * e1;
                    int sl0 = bS[r0] - b0, sl1 = bS[r1] - b0;
                    if (sl0 < NSLOT) {
                        float* d = &slots[(s * NSLOT + sl0) * 128 + col];
                        atomicAdd(d, v00);
                        atomicAdd(d + 1, v01);
                    } else {
                        float* d = &g_U[((long long)s * G + bS[r0]) * 128 + col];
                        atomicAdd(d, v00);
                        atomicAdd(d + 1, v01);
                    }
                    if (sl1 < NSLOT) {
                        float* d = &slots[(s * NSLOT + sl1) * 128 + col];
                        atomicAdd(d, v10);
                        atomicAdd(d + 1, v11);
                    } else {
                        float* d = &g_U[((long long)s * G + bS[r1]) * 128 + col];
                        atomicAdd(d, v10);
                        atomicAdd(d + 1, v11);
                    }
                }
        if (t < 32) {  // denominators
#pragma unroll
            for (int s = 0; s < 3; s++) {
                float e = eS[s * 32 + t];
                int sl = bS[t] - b0;
                if (sl < NSLOT) atomicAdd(&aD[s * NSLOT + sl], e);
                else atomicAdd(&g_Dn[s * G + bS[t]], e);
            }
        }
        __syncthreads();

        // ---- flush slots -> global, rezero
        for (int i = t; i < 3 * NSLOT * 128; i += 256) {
            float v = slots[i];
            if (v != 0.f) {
                int s = i >> 9, rest = i & 511, sl = rest >> 7, col = rest & 127;
                int seg = b0 + sl;
                if (seg < G)
                    atomicAdd(&g_U[((long long)s * G + seg) * 128 + col], v);
                slots[i] = 0.f;
            }
        }
        if (t < 3 * NSLOT) {
            float v = aD[t];
            if (v != 0.f) {
                int s = t / NSLOT, sl = t % NSLOT, seg = b0 + sl;
                if (seg < G) atomicAdd(&g_Dn[s * G + seg], v);
                aD[t] = 0.f;
            }
        }
        __syncthreads();
    }
}

__global__ void __launch_bounds__(256) transform_step(
    const float* __restrict__ U, const float* __restrict__ Dn,
    const float* __restrict__ xg_in, const float* __restrict__ tw,
    const float* __restrict__ tb, float* __restrict__ xg_out, int G) {
    __shared__ float cat[16][257];
    int t = threadIdx.x;
    int g0 = blockIdx.x * 16;
    for (int i = t; i < 16 * 256; i += 256) {
        int gi = i >> 8, k = i & 255;
        int g = g0 + gi;
        float v = 0.f;
        if (g < G) {
            if (k < 128) {
                float d = Dn[g];
                v = d > 0.f ? U[(size_t)g * 128 + k] / d : 0.f;
            } else {
                v = xg_in[(size_t)g * 128 + (k - 128)];
            }
        }
        cat[gi][k] = v;
    }
    __syncthreads();
    int col = t & 127, h8 = (t >> 7) * 8;
    float acc[8];
    float bias = tb[col];
#pragma unroll
    for (int gi = 0; gi < 8; gi++) acc[gi] = bias;
#pragma unroll 4
    for (int k = 0; k < 256; k++) {
        float wv = __ldg(tw + k * 128 + col);
#pragma unroll
        for (int gi = 0; gi < 8; gi++) acc[gi] += cat[h8 + gi][k] * wv;
    }
#pragma unroll
    for (int gi = 0; gi < 8; gi++) {
        int g = g0 + h8 + gi;
        if (g < G)
            xg_out[(size_t)g * 128 + col] = leaky1(acc[gi]) + cat[h8 + gi][128 + col];
    }
}

extern "C" void kernel_launch(void* const* d_in, const int* in_sizes, int n_in,
                              void* d_out, int out_size) {
    const float* x = (const float*)d_in[0];
    const float* xg0 = (const float*)d_in[1];
    const int* bp = (const int*)d_in[4];
    const float* gate_w = (const float*)d_in[n_in - 6];
    const float* gate_b = (const float*)d_in[n_in - 5];
    const float* feat_w = (const float*)d_in[n_in - 4];
    const float* feat_b = (const float*)d_in[n_in - 3];
    const float* tr_w = (const float*)d_in[n_in - 2];
    const float* tr_b = (const float*)d_in[n_in - 1];

    int N = in_sizes[0] / 128;
    int G = in_sizes[1] / 128;

    float* out = (float*)d_out;
    float* x_out = 0;
    float* xg_final = out;
    if ((long long)out_size >= (long long)N * 128 + (long long)G * 128) {
        x_out = out;
        xg_final = out + (size_t)N * 128;
    }

    cudaFuncSetAttribute(fused_pool, cudaFuncAttributeMaxDynamicSharedMemorySize,
                         SMEM_BYTES);

    init_kernel<<<256, 256>>>(bp, feat_w, N, G);

    int nsm = 148, dev = 0;
    cudaGetDevice(&dev);
    cudaDeviceGetAttribute(&nsm, cudaDevAttrMultiProcessorCount, dev);
    int ntiles = (N + 31) / 32;
    int grid = nsm < ntiles ? nsm : ntiles;
    fused_pool<<<grid, 256, SMEM_BYTES>>>(x, bp, gate_w, gate_b, feat_b, x_out,
                                          N, G, ntiles);

    float *dU, *dD, *dA, *dB;
    cudaGetSymbolAddress((void**)&dU, g_U);
    cudaGetSymbolAddress((void**)&dD, g_Dn);
    cudaGetSymbolAddress((void**)&dA, g_xgA);
    cudaGetSymbolAddress((void**)&dB, g_xgB);

    int tblk = (G + 15) / 16;
    transform_step<<<tblk, 256>>>(dU, dD, xg0, tr_w, tr_b, dA, G);
    transform_step<<<tblk, 256>>>(dU + (size_t)G * 128, dD + G, dA,
                                  tr_w + 256 * 128, tr_b + 128, dB, G);
    transform_step<<<tblk, 256>>>(dU + (size_t)2 * G * 128, dD + 2 * G, dB,
                                  tr_w + 2 * 256 * 128, tr_b + 2 * 128,
                                  xg_final, G);
}

// round 6
// speedup vs baseline: 1.8748x; 1.8748x over previous
#include <cuda_runtime.h>
#include <cuda_bf16.h>
#include <cstdint>

// ---------------------------------------------------------------------------
// PoolOnlyGNN — mma.sync bf16x3, persistent CTAs, lean staging epilogue.
// ---------------------------------------------------------------------------

#define MAXG  8192
#define NSLOT 4
#define THREADS 512

__device__ float g_U[3 * MAXG * 128];
__device__ float g_Dn[3 * MAXG];
__device__ int   g_is64;
__device__ unsigned short g_Wsw[6 * 16384];  // (Wh,Wl) x 3 steps, ldmatrix layout
__device__ float g_xgA[MAXG * 128];
__device__ float g_xgB[MAXG * 128];

__device__ __forceinline__ uint32_t smem_u32(const void* p) {
    uint32_t a;
    asm("{ .reg .u64 t; cvta.to.shared.u64 t, %1; cvt.u32.u64 %0, t; }"
        : "=r"(a) : "l"(p));
    return a;
}
__device__ __forceinline__ void ldsm4(uint32_t* r, uint32_t a) {
    asm volatile("ldmatrix.sync.aligned.m8n8.x4.shared.b16 {%0,%1,%2,%3}, [%4];"
                 : "=r"(r[0]), "=r"(r[1]), "=r"(r[2]), "=r"(r[3]) : "r"(a));
}
__device__ __forceinline__ void mma16816(float* c, const uint32_t* a,
                                         uint32_t b0, uint32_t b1) {
    asm volatile(
        "mma.sync.aligned.m16n8k16.row.col.f32.bf16.bf16.f32 "
        "{%0,%1,%2,%3}, {%4,%5,%6,%7}, {%8,%9}, {%0,%1,%2,%3};"
        : "+f"(c[0]), "+f"(c[1]), "+f"(c[2]), "+f"(c[3])
        : "r"(a[0]), "r"(a[1]), "r"(a[2]), "r"(a[3]), "r"(b0), "r"(b1));
}
__device__ __forceinline__ float leaky1(float v) { return v >= 0.f ? v : 0.01f * v; }

// element (row n, col k) byte offset in a 128x128 bf16 ldmatrix image:
// 256B per row, 16B chunks xor-swizzled by row&7.
__device__ __forceinline__ int img_off(int n, int k) {
    return n * 256 + (((k >> 3) ^ (n & 7)) << 4) + (k & 7) * 2;
}

__global__ void init_kernel(const int* __restrict__ bptr,
                            const float* __restrict__ feat_w, int N, int G) {
    int tid = blockIdx.x * blockDim.x + threadIdx.x;
    int stride = gridDim.x * blockDim.x;
    for (int i = tid; i < 3 * G * 128; i += stride) g_U[i] = 0.f;
    for (int i = tid; i < 3 * G; i += stride) g_Dn[i] = 0.f;
    for (int i = tid; i < 3 * 16384; i += stride) {
        int s = i >> 14, r = i & 16383;
        int k = r >> 7, n = r & 127;           // feat_w[s][k][n]
        float wv = feat_w[i];
        __nv_bfloat16 bh = __float2bfloat16(wv);
        __nv_bfloat16 bl = __float2bfloat16(wv - __bfloat162float(bh));
        int off = img_off(n, k) >> 1;
        g_Wsw[(2 * s) * 16384 + off] = *(const unsigned short*)&bh;
        g_Wsw[(2 * s + 1) * 16384 + off] = *(const unsigned short*)&bl;
    }
    if (tid == 0) {
        int probe = (N & 1) ? (N - 2) : (N - 1);
        if (probe < 0) probe = 0;
        g_is64 = (bptr[probe] == 0) ? 1 : 0;
    }
}

// smem byte offsets
#define OFF_W     0        // 196608 : 6 W images
#define OFF_XHI   196608   // 8192   : x hi (32 rows x 256B)
#define OFF_XLO   204800   // 8192
#define OFF_CST   212992   // 8448   : staging 16 x 132 f32
#define OFF_SLOT  221440   // 2048   : NSLOT x 128 f32
#define OFF_AD    223488   // 16
#define OFF_ES    223504   // 384    : e[3][32]
#define OFF_BS    223888   // 128    : batch id per row
#define OFF_GW    224016   // 1536
#define OFF_FB    225552   // 1536
#define SMEM_BYTES 227088

__global__ void __launch_bounds__(THREADS, 1) fused_pool(
    const float* __restrict__ x, const int* __restrict__ bptr,
    const float* __restrict__ gate_w, const float* __restrict__ gate_b,
    const float* __restrict__ feat_b, float* __restrict__ x_out,
    int N, int G, int ntiles) {
    extern __shared__ char sm[];
    float* Cst = (float*)(sm + OFF_CST);
    float* slots = (float*)(sm + OFF_SLOT);
    float* aD = (float*)(sm + OFF_AD);
    float* eS = (float*)(sm + OFF_ES);
    int* bS = (int*)(sm + OFF_BS);
    float* gws = (float*)(sm + OFF_GW);
    float* fbs = (float*)(sm + OFF_FB);
    const uint32_t sb = smem_u32(sm);
    const uint32_t xhiB = sb + OFF_XHI, xloB = sb + OFF_XLO;

    const int t = threadIdx.x, lane = t & 31, w = t >> 5;
    const int wg = w >> 3;            // warp-group: rows wg*16..wg*16+15
    const int n0 = (w & 7) * 16;      // 16 output cols per warp

    {  // stage the six 32KB W images once
        const int4* srcw = (const int4*)g_Wsw;
        int4* dstw = (int4*)sm;
        for (int i = t; i < 12288; i += THREADS) dstw[i] = srcw[i];
    }
    for (int i = t; i < 384; i += THREADS) { gws[i] = gate_w[i]; fbs[i] = feat_b[i]; }
    __syncthreads();

    const int strb = g_is64 ? 2 : 1;
    const float gb0 = gate_b[0], gb1 = gate_b[1], gb2 = gate_b[2];
    const int lr = t >> 4, lp = t & 15;  // loader: row 0..31, 8-col part

    // per-lane fragment addressing constants (R4-proven)
    const int arow = wg * 16 + (lane & 15);
    const uint32_t abase = (uint32_t)arow * 256;
    const int a_sw = arow & 7, a_odd = lane >> 4;
    const int brow = n0 + (lane & 7) + ((lane >> 4) << 3);
    const uint32_t bbase = (uint32_t)brow * 256;
    const int b_sw = brow & 7, b_odd = (lane >> 3) & 1;

    for (int tile = blockIdx.x; tile < ntiles; tile += gridDim.x) {
        const long long row0 = (long long)tile * 32;

        // ---- loader: x rows, gates, bf16 split, x copy
        {
            const long long grow = row0 + lr;
            const bool ok = grow < (long long)N;
            const long long crow = ok ? grow : (long long)N - 1;
            const float4* xr = ((const float4*)x) + crow * 32;
            float4 fa = ok ? __ldg(xr + lp * 2) : make_float4(0.f, 0.f, 0.f, 0.f);
            float4 fb4 = ok ? __ldg(xr + lp * 2 + 1) : make_float4(0.f, 0.f, 0.f, 0.f);
            float p0 = 0.f, p1 = 0.f, p2 = 0.f;
            const float* gv = &gws[lp * 8];
            p0 = fa.x * gv[0] + fa.y * gv[1] + fa.z * gv[2] + fa.w * gv[3] +
                 fb4.x * gv[4] + fb4.y * gv[5] + fb4.z * gv[6] + fb4.w * gv[7];
            gv += 128;
            p1 = fa.x * gv[0] + fa.y * gv[1] + fa.z * gv[2] + fa.w * gv[3] +
                 fb4.x * gv[4] + fb4.y * gv[5] + fb4.z * gv[6] + fb4.w * gv[7];
            gv += 128;
            p2 = fa.x * gv[0] + fa.y * gv[1] + fa.z * gv[2] + fa.w * gv[3] +
                 fb4.x * gv[4] + fb4.y * gv[5] + fb4.z * gv[6] + fb4.w * gv[7];
#pragma unroll
            for (int o = 8; o > 0; o >>= 1) {
                p0 += __shfl_down_sync(0xffffffffu, p0, o, 16);
                p1 += __shfl_down_sync(0xffffffffu, p1, o, 16);
                p2 += __shfl_down_sync(0xffffffffu, p2, o, 16);
            }
            if (lp == 0) {
                eS[0 * 32 + lr] = ok ? expf(p0 + gb0) : 0.f;
                eS[1 * 32 + lr] = ok ? expf(p1 + gb1) : 0.f;
                eS[2 * 32 + lr] = ok ? expf(p2 + gb2) : 0.f;
                bS[lr] = bptr[crow * strb];
            }
            // bf16 hi/lo split -> one 16B chunk each
            __nv_bfloat162 h0 = __floats2bfloat162_rn(fa.x, fa.y);
            __nv_bfloat162 h1 = __floats2bfloat162_rn(fa.z, fa.w);
            __nv_bfloat162 h2 = __floats2bfloat162_rn(fb4.x, fb4.y);
            __nv_bfloat162 h3 = __floats2bfloat162_rn(fb4.z, fb4.w);
            float2 q0 = __bfloat1622float2(h0), q1 = __bfloat1622float2(h1);
            float2 q2 = __bfloat1622float2(h2), q3 = __bfloat1622float2(h3);
            __nv_bfloat162 l0 = __floats2bfloat162_rn(fa.x - q0.x, fa.y - q0.y);
            __nv_bfloat162 l1 = __floats2bfloat162_rn(fa.z - q1.x, fa.w - q1.y);
            __nv_bfloat162 l2 = __floats2bfloat162_rn(fb4.x - q2.x, fb4.y - q2.y);
            __nv_bfloat162 l3 = __floats2bfloat162_rn(fb4.z - q3.x, fb4.w - q3.y);
            int off = lr * 256 + ((lp ^ (lr & 7)) << 4);
            *(uint4*)(sm + OFF_XHI + off) = make_uint4(
                *(uint32_t*)&h0, *(uint32_t*)&h1, *(uint32_t*)&h2, *(uint32_t*)&h3);
            *(uint4*)(sm + OFF_XLO + off) = make_uint4(
                *(uint32_t*)&l0, *(uint32_t*)&l1, *(uint32_t*)&l2, *(uint32_t*)&l3);
            if (ok && x_out) {
                ((float4*)x_out)[grow * 32 + lp * 2] = fa;
                ((float4*)x_out)[grow * 32 + lp * 2 + 1] = fb4;
            }
        }
        __syncthreads();
        const int b0 = bS[0];

        for (int s = 0; s < 3; s++) {
            // zero slots (+aD) for this step
            for (int i = t; i < NSLOT * 128 + NSLOT; i += THREADS) slots[i] = 0.f;

            // ---- GEMM: warp = 16 rows (wg) x 16 cols (n0), bf16x3
            float Ca[2][4], Cb[2][4];
#pragma unroll
            for (int nf = 0; nf < 2; nf++)
#pragma unroll
                for (int q = 0; q < 4; q++) { Ca[nf][q] = 0.f; Cb[nf][q] = 0.f; }
            const uint32_t whB = sb + (2 * s) * 32768;
            const uint32_t wlB = sb + (2 * s + 1) * 32768;
#pragma unroll
            for (int kb = 0; kb < 8; kb++) {
                uint32_t Ah[4], Al[4], Bh[4], Bl[4];
                uint32_t aoff = abase + (((2 * kb + a_odd) ^ a_sw) << 4);
                ldsm4(Ah, xhiB + aoff);
                ldsm4(Al, xloB + aoff);
                uint32_t boff = bbase + (((2 * kb + b_odd) ^ b_sw) << 4);
                ldsm4(Bh, whB + boff);
                ldsm4(Bl, wlB + boff);
#pragma unroll
                for (int nf = 0; nf < 2; nf++) {
                    mma16816(Ca[nf], Ah, Bh[2 * nf], Bh[2 * nf + 1]);
                    mma16816(Cb[nf], Al, Bh[2 * nf], Bh[2 * nf + 1]);
                    mma16816(Cb[nf], Ah, Bl[2 * nf], Bl[2 * nf + 1]);
                }
            }
#pragma unroll
            for (int nf = 0; nf < 2; nf++)
#pragma unroll
                for (int q = 0; q < 4; q++) Ca[nf][q] += Cb[nf][q];

            // denominators (once per step)
            if (t < 32) {
                float e = eS[s * 32 + t];
                int sl = bS[t] - b0;
                if (sl < NSLOT) atomicAdd(&aD[sl], e);
                else atomicAdd(&g_Dn[s * G + bS[t]], e);
            }

            // ---- two staging phases: rows 0-15 (wg0), rows 16-31 (wg1)
#pragma unroll
            for (int ph = 0; ph < 2; ph++) {
                if (wg == ph) {
                    int g = lane >> 2, tq = lane & 3;
#pragma unroll
                    for (int nf = 0; nf < 2; nf++) {
                        int col = n0 + nf * 8 + tq * 2;
                        *(float2*)&Cst[g * 132 + col] =
                            make_float2(Ca[nf][0], Ca[nf][1]);
                        *(float2*)&Cst[(g + 8) * 132 + col] =
                            make_float2(Ca[nf][2], Ca[nf][3]);
                    }
                }
                __syncthreads();
                if (t < 256) {
                    int c = t & 127, h = t >> 7;
                    int rb = ph * 16 + h * 8;
                    float fb = fbs[s * 128 + c];
                    int curb = bS[rb];
                    float acc = 0.f;
#pragma unroll
                    for (int rr = 0; rr < 8; rr++) {
                        int row = rb + rr;
                        int b = bS[row];
                        if (b != curb) {
                            int sl = curb - b0;
                            if (sl < NSLOT) atomicAdd(&slots[sl * 128 + c], acc);
                            else atomicAdd(&g_U[((long long)s * G + curb) * 128 + c], acc);
                            acc = 0.f;
                            curb = b;
                        }
                        float v = Cst[(row - ph * 16) * 132 + c];
                        acc += leaky1(v + fb) * eS[s * 32 + row];
                    }
                    int sl = curb - b0;
                    if (sl < NSLOT) atomicAdd(&slots[sl * 128 + c], acc);
                    else atomicAdd(&g_U[((long long)s * G + curb) * 128 + c], acc);
                }
                __syncthreads();
            }

            // ---- flush slots -> global
            int span = bS[31] - b0 + 1;
            if (span > NSLOT) span = NSLOT;
            for (int i = t; i < span * 128; i += THREADS) {
                int slot = i >> 7, c = i & 127;
                float v = slots[i];
                if (v != 0.f)
                    atomicAdd(&g_U[((long long)s * G + b0 + slot) * 128 + c], v);
            }
            if (t < span) {
                float v = aD[t];
                if (v != 0.f) atomicAdd(&g_Dn[s * G + b0 + t], v);
            }
            __syncthreads();
        }
    }
}

__global__ void __launch_bounds__(256) transform_step(
    const float* __restrict__ U, const float* __restrict__ Dn,
    const float* __restrict__ xg_in, const float* __restrict__ tw,
    const float* __restrict__ tb, float* __restrict__ xg_out, int G) {
    __shared__ float cat[16][257];
    int t = threadIdx.x;
    int g0 = blockIdx.x * 16;
    for (int i = t; i < 16 * 256; i += 256) {
        int gi = i >> 8, k = i & 255;
        int g = g0 + gi;
        float v = 0.f;
        if (g < G) {
            if (k < 128) {
                float d = Dn[g];
                v = d > 0.f ? U[(size_t)g * 128 + k] / d : 0.f;
            } else {
                v = xg_in[(size_t)g * 128 + (k - 128)];
            }
        }
        cat[gi][k] = v;
    }
    __syncthreads();
    int col = t & 127, h8 = (t >> 7) * 8;
    float acc[8];
    float bias = tb[col];
#pragma unroll
    for (int gi = 0; gi < 8; gi++) acc[gi] = bias;
#pragma unroll 4
    for (int k = 0; k < 256; k++) {
        float wv = __ldg(tw + k * 128 + col);
#pragma unroll
        for (int gi = 0; gi < 8; gi++) acc[gi] += cat[h8 + gi][k] * wv;
    }
#pragma unroll
    for (int gi = 0; gi < 8; gi++) {
        int g = g0 + h8 + gi;
        if (g < G)
            xg_out[(size_t)g * 128 + col] = leaky1(acc[gi]) + cat[h8 + gi][128 + col];
    }
}

extern "C" void kernel_launch(void* const* d_in, const int* in_sizes, int n_in,
                              void* d_out, int out_size) {
    const float* x = (const float*)d_in[0];
    const float* xg0 = (const float*)d_in[1];
    const int* bp = (const int*)d_in[4];
    const float* gate_w = (const float*)d_in[n_in - 6];
    const float* gate_b = (const float*)d_in[n_in - 5];
    const float* feat_w = (const float*)d_in[n_in - 4];
    const float* feat_b = (const float*)d_in[n_in - 3];
    const float* tr_w = (const float*)d_in[n_in - 2];
    const float* tr_b = (const float*)d_in[n_in - 1];

    int N = in_sizes[0] / 128;
    int G = in_sizes[1] / 128;

    float* out = (float*)d_out;
    float* x_out = 0;
    float* xg_final = out;
    if ((long long)out_size >= (long long)N * 128 + (long long)G * 128) {
        x_out = out;
        xg_final = out + (size_t)N * 128;
    }

    cudaFuncSetAttribute(fused_pool, cudaFuncAttributeMaxDynamicSharedMemorySize,
                         SMEM_BYTES);

    init_kernel<<<256, 256>>>(bp, feat_w, N, G);

    int nsm = 148, dev = 0;
    cudaGetDevice(&dev);
    cudaDeviceGetAttribute(&nsm, cudaDevAttrMultiProcessorCount, dev);
    int ntiles = (N + 31) / 32;
    int grid = nsm < ntiles ? nsm : ntiles;
    fused_pool<<<grid, THREADS, SMEM_BYTES>>>(x, bp, gate_w, gate_b, feat_b,
                                              x_out, N, G, ntiles);

    float *dU, *dD, *dA, *dB;
    cudaGetSymbolAddress((void**)&dU, g_U);
    cudaGetSymbolAddress((void**)&dD, g_Dn);
    cudaGetSymbolAddress((void**)&dA, g_xgA);
    cudaGetSymbolAddress((void**)&dB, g_xgB);

    int tblk = (G + 15) / 16;
    transform_step<<<tblk, 256>>>(dU, dD, xg0, tr_w, tr_b, dA, G);
    transform_step<<<tblk, 256>>>(dU + (size_t)G * 128, dD + G, dA,
                                  tr_w + 256 * 128, tr_b + 128, dB, G);
    transform_step<<<tblk, 256>>>(dU + (size_t)2 * G * 128, dD + 2 * G, dB,
                                  tr_w + 2 * 256 * 128, tr_b + 2 * 128,
                                  xg_final, G);
}

// round 7
// speedup vs baseline: 3.9772x; 2.1214x over previous
#include <cuda_runtime.h>
#include <cuda_bf16.h>
#include <cstdint>

// ---------------------------------------------------------------------------
// PoolOnlyGNN — mma.sync bf16x3, persistent CTAs, barrier-free register
// epilogue (xor-shuffle segment fold + spread global REDs).
// ---------------------------------------------------------------------------

#define MAXG  8192
#define THREADS 512

__device__ float g_U[3 * MAXG * 128];
__device__ float g_Dn[3 * MAXG];
__device__ int   g_is64;
__device__ unsigned short g_Wsw[6 * 16384];  // (Wh,Wl) x 3 steps, ldmatrix layout
__device__ float g_xgA[MAXG * 128];
__device__ float g_xgB[MAXG * 128];

__device__ __forceinline__ uint32_t smem_u32(const void* p) {
    uint32_t a;
    asm("{ .reg .u64 t; cvta.to.shared.u64 t, %1; cvt.u32.u64 %0, t; }"
        : "=r"(a) : "l"(p));
    return a;
}
__device__ __forceinline__ void ldsm4(uint32_t* r, uint32_t a) {
    asm volatile("ldmatrix.sync.aligned.m8n8.x4.shared.b16 {%0,%1,%2,%3}, [%4];"
                 : "=r"(r[0]), "=r"(r[1]), "=r"(r[2]), "=r"(r[3]) : "r"(a));
}
__device__ __forceinline__ void mma16816(float* c, const uint32_t* a,
                                         uint32_t b0, uint32_t b1) {
    asm volatile(
        "mma.sync.aligned.m16n8k16.row.col.f32.bf16.bf16.f32 "
        "{%0,%1,%2,%3}, {%4,%5,%6,%7}, {%8,%9}, {%0,%1,%2,%3};"
        : "+f"(c[0]), "+f"(c[1]), "+f"(c[2]), "+f"(c[3])
        : "r"(a[0]), "r"(a[1]), "r"(a[2]), "r"(a[3]), "r"(b0), "r"(b1));
}
__device__ __forceinline__ float leaky1(float v) { return v >= 0.f ? v : 0.01f * v; }

// element (row n, col k) byte offset in a 128x128 bf16 ldmatrix image:
// 256B per row, 16B chunks xor-swizzled by row&7.
__device__ __forceinline__ int img_off(int n, int k) {
    return n * 256 + (((k >> 3) ^ (n & 7)) << 4) + (k & 7) * 2;
}

__global__ void init_kernel(const int* __restrict__ bptr,
                            const float* __restrict__ feat_w, int N, int G) {
    int tid = blockIdx.x * blockDim.x + threadIdx.x;
    int stride = gridDim.x * blockDim.x;
    for (int i = tid; i < 3 * G * 128; i += stride) g_U[i] = 0.f;
    for (int i = tid; i < 3 * G; i += stride) g_Dn[i] = 0.f;
    for (int i = tid; i < 3 * 16384; i += stride) {
        int s = i >> 14, r = i & 16383;
        int k = r >> 7, n = r & 127;           // feat_w[s][k][n]
        float wv = feat_w[i];
        __nv_bfloat16 bh = __float2bfloat16(wv);
        __nv_bfloat16 bl = __float2bfloat16(wv - __bfloat162float(bh));
        int off = img_off(n, k) >> 1;
        g_Wsw[(2 * s) * 16384 + off] = *(const unsigned short*)&bh;
        g_Wsw[(2 * s + 1) * 16384 + off] = *(const unsigned short*)&bl;
    }
    if (tid == 0) {
        int probe = (N & 1) ? (N - 2) : (N - 1);
        if (probe < 0) probe = 0;
        g_is64 = (bptr[probe] == 0) ? 1 : 0;
    }
}

// smem byte offsets
#define OFF_W     0        // 196608 : 6 W images
#define OFF_XHI   196608   // 8192   : x hi (32 rows x 256B)
#define OFF_XLO   204800   // 8192
#define OFF_ES    212992   // 384    : e[3][32]
#define OFF_BS    213376   // 128    : batch id per row
#define OFF_GW    213504   // 1536
#define OFF_FB    215040   // 1536
#define SMEM_BYTES 216576

__global__ void __launch_bounds__(THREADS, 1) fused_pool(
    const float* __restrict__ x, const int* __restrict__ bptr,
    const float* __restrict__ gate_w, const float* __restrict__ gate_b,
    const float* __restrict__ feat_b, float* __restrict__ x_out,
    int N, int G, int ntiles) {
    extern __shared__ char sm[];
    float* eS = (float*)(sm + OFF_ES);
    int* bS = (int*)(sm + OFF_BS);
    float* gws = (float*)(sm + OFF_GW);
    float* fbs = (float*)(sm + OFF_FB);
    const uint32_t sb = smem_u32(sm);
    const uint32_t xhiB = sb + OFF_XHI, xloB = sb + OFF_XLO;

    const int t = threadIdx.x, lane = t & 31, w = t >> 5;
    const int wg = w >> 3;            // row-group: rows wg*16..wg*16+15
    const int n0 = (w & 7) * 16;      // 16 output cols per warp
    const bool doDn = ((w & 7) == 0); // denominator owner per row-group

    {  // stage the six 32KB W images once
        const int4* srcw = (const int4*)g_Wsw;
        int4* dstw = (int4*)sm;
        for (int i = t; i < 12288; i += THREADS) dstw[i] = srcw[i];
    }
    for (int i = t; i < 384; i += THREADS) { gws[i] = gate_w[i]; fbs[i] = feat_b[i]; }
    __syncthreads();

    const int strb = g_is64 ? 2 : 1;
    const float gb0 = gate_b[0], gb1 = gate_b[1], gb2 = gate_b[2];
    const int lr = t >> 4, lp = t & 15;  // loader: row 0..31, 8-col part

    // per-lane fragment addressing constants (R4/R6-proven)
    const int arow = wg * 16 + (lane & 15);
    const uint32_t abase = (uint32_t)arow * 256;
    const int a_sw = arow & 7, a_odd = lane >> 4;
    const int brow = n0 + (lane & 7) + ((lane >> 4) << 3);
    const uint32_t bbase = (uint32_t)brow * 256;
    const int b_sw = brow & 7, b_odd = (lane >> 3) & 1;

    const int g = lane >> 2, tq = lane & 3;
    const int rg = wg * 16;

    for (int tile = blockIdx.x; tile < ntiles; tile += gridDim.x) {
        const long long row0 = (long long)tile * 32;

        // ---- loader: x rows, gates, bf16 split, x copy
        {
            const long long grow = row0 + lr;
            const bool ok = grow < (long long)N;
            const long long crow = ok ? grow : (long long)N - 1;
            const float4* xr = ((const float4*)x) + crow * 32;
            float4 fa = ok ? __ldg(xr + lp * 2) : make_float4(0.f, 0.f, 0.f, 0.f);
            float4 fb4 = ok ? __ldg(xr + lp * 2 + 1) : make_float4(0.f, 0.f, 0.f, 0.f);
            float p0, p1, p2;
            const float* gv = &gws[lp * 8];
            p0 = fa.x * gv[0] + fa.y * gv[1] + fa.z * gv[2] + fa.w * gv[3] +
                 fb4.x * gv[4] + fb4.y * gv[5] + fb4.z * gv[6] + fb4.w * gv[7];
            gv += 128;
            p1 = fa.x * gv[0] + fa.y * gv[1] + fa.z * gv[2] + fa.w * gv[3] +
                 fb4.x * gv[4] + fb4.y * gv[5] + fb4.z * gv[6] + fb4.w * gv[7];
            gv += 128;
            p2 = fa.x * gv[0] + fa.y * gv[1] + fa.z * gv[2] + fa.w * gv[3] +
                 fb4.x * gv[4] + fb4.y * gv[5] + fb4.z * gv[6] + fb4.w * gv[7];
#pragma unroll
            for (int o = 8; o > 0; o >>= 1) {
                p0 += __shfl_down_sync(0xffffffffu, p0, o, 16);
                p1 += __shfl_down_sync(0xffffffffu, p1, o, 16);
                p2 += __shfl_down_sync(0xffffffffu, p2, o, 16);
            }
            if (lp == 0) {
                eS[0 * 32 + lr] = ok ? expf(p0 + gb0) : 0.f;
                eS[1 * 32 + lr] = ok ? expf(p1 + gb1) : 0.f;
                eS[2 * 32 + lr] = ok ? expf(p2 + gb2) : 0.f;
                bS[lr] = bptr[crow * strb];
            }
            __nv_bfloat162 h0 = __floats2bfloat162_rn(fa.x, fa.y);
            __nv_bfloat162 h1 = __floats2bfloat162_rn(fa.z, fa.w);
            __nv_bfloat162 h2 = __floats2bfloat162_rn(fb4.x, fb4.y);
            __nv_bfloat162 h3 = __floats2bfloat162_rn(fb4.z, fb4.w);
            float2 q0 = __bfloat1622float2(h0), q1 = __bfloat1622float2(h1);
            float2 q2 = __bfloat1622float2(h2), q3 = __bfloat1622float2(h3);
            __nv_bfloat162 l0 = __floats2bfloat162_rn(fa.x - q0.x, fa.y - q0.y);
            __nv_bfloat162 l1 = __floats2bfloat162_rn(fa.z - q1.x, fa.w - q1.y);
            __nv_bfloat162 l2 = __floats2bfloat162_rn(fb4.x - q2.x, fb4.y - q2.y);
            __nv_bfloat162 l3 = __floats2bfloat162_rn(fb4.z - q3.x, fb4.w - q3.y);
            int off = lr * 256 + ((lp ^ (lr & 7)) << 4);
            *(uint4*)(sm + OFF_XHI + off) = make_uint4(
                *(uint32_t*)&h0, *(uint32_t*)&h1, *(uint32_t*)&h2, *(uint32_t*)&h3);
            *(uint4*)(sm + OFF_XLO + off) = make_uint4(
                *(uint32_t*)&l0, *(uint32_t*)&l1, *(uint32_t*)&l2, *(uint32_t*)&l3);
            if (ok && x_out) {
                ((float4*)x_out)[grow * 32 + lp * 2] = fa;
                ((float4*)x_out)[grow * 32 + lp * 2 + 1] = fb4;
            }
        }
        __syncthreads();

        // per-warp segment info (same for all steps)
        const int segLo = bS[rg], segHi = bS[rg + 15];
        const int mybA = bS[rg + g], mybB = bS[rg + g + 8];

#pragma unroll
        for (int s = 0; s < 3; s++) {
            // ---- GEMM: warp = 16 rows x 16 cols, bf16x3
            float Ca[2][4], Cb[2][4];
#pragma unroll
            for (int nf = 0; nf < 2; nf++)
#pragma unroll
                for (int q = 0; q < 4; q++) { Ca[nf][q] = 0.f; Cb[nf][q] = 0.f; }
            const uint32_t whB = sb + (2 * s) * 32768;
            const uint32_t wlB = sb + (2 * s + 1) * 32768;
#pragma unroll
            for (int kb = 0; kb < 8; kb++) {
                uint32_t Ah[4], Al[4], Bh[4], Bl[4];
                uint32_t aoff = abase + (((2 * kb + a_odd) ^ a_sw) << 4);
                ldsm4(Ah, xhiB + aoff);
                ldsm4(Al, xloB + aoff);
                uint32_t boff = bbase + (((2 * kb + b_odd) ^ b_sw) << 4);
                ldsm4(Bh, whB + boff);
                ldsm4(Bl, wlB + boff);
#pragma unroll
                for (int nf = 0; nf < 2; nf++) {
                    mma16816(Ca[nf], Ah, Bh[2 * nf], Bh[2 * nf + 1]);
                    mma16816(Cb[nf], Al, Bh[2 * nf], Bh[2 * nf + 1]);
                    mma16816(Cb[nf], Ah, Bl[2 * nf], Bl[2 * nf + 1]);
                }
            }

            // ---- register epilogue: bias+leaky+e-weight, shuffle fold, RED
            const float eA = eS[s * 32 + rg + g];
            const float eB = eS[s * 32 + rg + g + 8];
            const int c0 = n0 + tq * 2, c1 = n0 + 8 + tq * 2;
            const float b00 = fbs[s * 128 + c0], b01 = fbs[s * 128 + c0 + 1];
            const float b10 = fbs[s * 128 + c1], b11 = fbs[s * 128 + c1 + 1];
            float v00 = leaky1(Ca[0][0] + Cb[0][0] + b00) * eA;
            float v01 = leaky1(Ca[0][1] + Cb[0][1] + b01) * eA;
            float v02 = leaky1(Ca[0][2] + Cb[0][2] + b00) * eB;
            float v03 = leaky1(Ca[0][3] + Cb[0][3] + b01) * eB;
            float v10 = leaky1(Ca[1][0] + Cb[1][0] + b10) * eA;
            float v11 = leaky1(Ca[1][1] + Cb[1][1] + b11) * eA;
            float v12 = leaky1(Ca[1][2] + Cb[1][2] + b10) * eB;
            float v13 = leaky1(Ca[1][3] + Cb[1][3] + b11) * eB;

            for (int seg = segLo; seg <= segHi; ++seg) {
                bool mA = (mybA == seg), mB = (mybB == seg);
                float t00 = (mA ? v00 : 0.f) + (mB ? v02 : 0.f);
                float t01 = (mA ? v01 : 0.f) + (mB ? v03 : 0.f);
                float t10 = (mA ? v10 : 0.f) + (mB ? v12 : 0.f);
                float t11 = (mA ? v11 : 0.f) + (mB ? v13 : 0.f);
                float te = (tq == 0) ? ((mA ? eA : 0.f) + (mB ? eB : 0.f)) : 0.f;
#pragma unroll
                for (int o = 4; o <= 16; o <<= 1) {
                    t00 += __shfl_xor_sync(0xffffffffu, t00, o);
                    t01 += __shfl_xor_sync(0xffffffffu, t01, o);
                    t10 += __shfl_xor_sync(0xffffffffu, t10, o);
                    t11 += __shfl_xor_sync(0xffffffffu, t11, o);
                    te += __shfl_xor_sync(0xffffffffu, te, o);
                }
                if (lane < 4) {
                    float* du = &g_U[((long long)s * G + seg) * 128];
                    atomicAdd(du + c0, t00);
                    atomicAdd(du + c0 + 1, t01);
                    atomicAdd(du + c1, t10);
                    atomicAdd(du + c1 + 1, t11);
                    if (doDn && lane == 0) atomicAdd(&g_Dn[s * G + seg], te);
                }
            }
        }
        __syncthreads();  // protect x tile before next loader pass
    }
}

__global__ void __launch_bounds__(256) transform_step(
    const float* __restrict__ U, const float* __restrict__ Dn,
    const float* __restrict__ xg_in, const float* __restrict__ tw,
    const float* __restrict__ tb, float* __restrict__ xg_out, int G) {
    __shared__ float cat[16][257];
    int t = threadIdx.x;
    int g0 = blockIdx.x * 16;
    for (int i = t; i < 16 * 256; i += 256) {
        int gi = i >> 8, k = i & 255;
        int g = g0 + gi;
        float v = 0.f;
        if (g < G) {
            if (k < 128) {
                float d = Dn[g];
                v = d > 0.f ? U[(size_t)g * 128 + k] / d : 0.f;
            } else {
                v = xg_in[(size_t)g * 128 + (k - 128)];
            }
        }
        cat[gi][k] = v;
    }
    __syncthreads();
    int col = t & 127, h8 = (t >> 7) * 8;
    float acc[8];
    float bias = tb[col];
#pragma unroll
    for (int gi = 0; gi < 8; gi++) acc[gi] = bias;
#pragma unroll 4
    for (int k = 0; k < 256; k++) {
        float wv = __ldg(tw + k * 128 + col);
#pragma unroll
        for (int gi = 0; gi < 8; gi++) acc[gi] += cat[h8 + gi][k] * wv;
    }
#pragma unroll
    for (int gi = 0; gi < 8; gi++) {
        int g = g0 + h8 + gi;
        if (g < G)
            xg_out[(size_t)g * 128 + col] = leaky1(acc[gi]) + cat[h8 + gi][128 + col];
    }
}

extern "C" void kernel_launch(void* const* d_in, const int* in_sizes, int n_in,
                              void* d_out, int out_size) {
    const float* x = (const float*)d_in[0];
    const float* xg0 = (const float*)d_in[1];
    const int* bp = (const int*)d_in[4];
    const float* gate_w = (const float*)d_in[n_in - 6];
    const float* gate_b = (const float*)d_in[n_in - 5];
    const float* feat_w = (const float*)d_in[n_in - 4];
    const float* feat_b = (const float*)d_in[n_in - 3];
    const float* tr_w = (const float*)d_in[n_in - 2];
    const float* tr_b = (const float*)d_in[n_in - 1];

    int N = in_sizes[0] / 128;
    int G = in_sizes[1] / 128;

    float* out = (float*)d_out;
    float* x_out = 0;
    float* xg_final = out;
    if ((long long)out_size >= (long long)N * 128 + (long long)G * 128) {
        x_out = out;
        xg_final = out + (size_t)N * 128;
    }

    cudaFuncSetAttribute(fused_pool, cudaFuncAttributeMaxDynamicSharedMemorySize,
                         SMEM_BYTES);

    init_kernel<<<512, 256>>>(bp, feat_w, N, G);

    int nsm = 148, dev = 0;
    cudaGetDevice(&dev);
    cudaDeviceGetAttribute(&nsm, cudaDevAttrMultiProcessorCount, dev);
    int ntiles = (N + 31) / 32;
    int grid = nsm < ntiles ? nsm : ntiles;
    fused_pool<<<grid, THREADS, SMEM_BYTES>>>(x, bp, gate_w, gate_b, feat_b,
                                              x_out, N, G, ntiles);

    float *dU, *dD, *dA, *dB;
    cudaGetSymbolAddress((void**)&dU, g_U);
    cudaGetSymbolAddress((void**)&dD, g_Dn);
    cudaGetSymbolAddress((void**)&dA, g_xgA);
    cudaGetSymbolAddress((void**)&dB, g_xgB);

    int tblk = (G + 15) / 16;
    transform_step<<<tblk, 256>>>(dU, dD, xg0, tr_w, tr_b, dA, G);
    transform_step<<<tblk, 256>>>(dU + (size_t)G * 128, dD + G, dA,
                                  tr_w + 256 * 128, tr_b + 128, dB, G);
    transform_step<<<tblk, 256>>>(dU + (size_t)2 * G * 128, dD + 2 * G, dB,
                                  tr_w + 2 * 256 * 128, tr_b + 2 * 128,
                                  xg_final, G);
}

// round 8
// speedup vs baseline: 4.0039x; 1.0067x over previous
#include <cuda_runtime.h>
#include <cuda_bf16.h>
#include <cstdint>

// ---------------------------------------------------------------------------
// PoolOnlyGNN — mma.sync bf16x3, persistent CTAs, 64-row tiles,
// cross-tile register prefetch, barrier-free register epilogue.
// ---------------------------------------------------------------------------

#define MAXG  8192
#define THREADS 512

__device__ float g_U[3 * MAXG * 128];
__device__ float g_Dn[3 * MAXG];
__device__ int   g_is64;
__device__ unsigned short g_Wsw[6 * 16384];  // (Wh,Wl) x 3 steps, ldmatrix layout
__device__ float g_xgA[MAXG * 128];
__device__ float g_xgB[MAXG * 128];

__device__ __forceinline__ uint32_t smem_u32(const void* p) {
    uint32_t a;
    asm("{ .reg .u64 t; cvta.to.shared.u64 t, %1; cvt.u32.u64 %0, t; }"
        : "=r"(a) : "l"(p));
    return a;
}
__device__ __forceinline__ void ldsm4(uint32_t* r, uint32_t a) {
    asm volatile("ldmatrix.sync.aligned.m8n8.x4.shared.b16 {%0,%1,%2,%3}, [%4];"
                 : "=r"(r[0]), "=r"(r[1]), "=r"(r[2]), "=r"(r[3]) : "r"(a));
}
__device__ __forceinline__ void mma16816(float* c, const uint32_t* a,
                                         uint32_t b0, uint32_t b1) {
    asm volatile(
        "mma.sync.aligned.m16n8k16.row.col.f32.bf16.bf16.f32 "
        "{%0,%1,%2,%3}, {%4,%5,%6,%7}, {%8,%9}, {%0,%1,%2,%3};"
        : "+f"(c[0]), "+f"(c[1]), "+f"(c[2]), "+f"(c[3])
        : "r"(a[0]), "r"(a[1]), "r"(a[2]), "r"(a[3]), "r"(b0), "r"(b1));
}
__device__ __forceinline__ float leaky1(float v) { return v >= 0.f ? v : 0.01f * v; }

// element (row n, col k) byte offset in a 128x128 bf16 ldmatrix image:
// 256B per row, 16B chunks xor-swizzled by row&7.
__device__ __forceinline__ int img_off(int n, int k) {
    return n * 256 + (((k >> 3) ^ (n & 7)) << 4) + (k & 7) * 2;
}

__global__ void init_kernel(const int* __restrict__ bptr,
                            const float* __restrict__ feat_w, int N, int G) {
    int tid = blockIdx.x * blockDim.x + threadIdx.x;
    int stride = gridDim.x * blockDim.x;
    for (int i = tid; i < 3 * G * 128; i += stride) g_U[i] = 0.f;
    for (int i = tid; i < 3 * G; i += stride) g_Dn[i] = 0.f;
    for (int i = tid; i < 3 * 16384; i += stride) {
        int s = i >> 14, r = i & 16383;
        int k = r >> 7, n = r & 127;           // feat_w[s][k][n]
        float wv = feat_w[i];
        __nv_bfloat16 bh = __float2bfloat16(wv);
        __nv_bfloat16 bl = __float2bfloat16(wv - __bfloat162float(bh));
        int off = img_off(n, k) >> 1;
        g_Wsw[(2 * s) * 16384 + off] = *(const unsigned short*)&bh;
        g_Wsw[(2 * s + 1) * 16384 + off] = *(const unsigned short*)&bl;
    }
    if (tid == 0) {
        int probe = (N & 1) ? (N - 2) : (N - 1);
        if (probe < 0) probe = 0;
        g_is64 = (bptr[probe] == 0) ? 1 : 0;
    }
}

// smem byte offsets
#define OFF_W     0        // 196608 : 6 W images
#define OFF_XHI   196608   // 16384  : x hi (64 rows x 256B)
#define OFF_XLO   212992   // 16384
#define OFF_ES    229376   // 768    : e[3][64]
#define OFF_BS    230144   // 256    : batch id per row
#define OFF_FB    230400   // 1536   : feat_b
#define SMEM_BYTES 231936

__global__ void __launch_bounds__(THREADS, 1) fused_pool(
    const float* __restrict__ x, const int* __restrict__ bptr,
    const float* __restrict__ gate_w, const float* __restrict__ gate_b,
    const float* __restrict__ feat_b, float* __restrict__ x_out,
    int N, int G, int ntiles) {
    extern __shared__ char sm[];
    float* eS = (float*)(sm + OFF_ES);
    int* bS = (int*)(sm + OFF_BS);
    float* fbs = (float*)(sm + OFF_FB);
    const uint32_t sb = smem_u32(sm);
    const uint32_t xhiB = sb + OFF_XHI, xloB = sb + OFF_XLO;

    const int t = threadIdx.x, lane = t & 31, w = t >> 5;
    const int rg = (w >> 2) * 16;     // row-group base (4 groups of 16 rows)
    const int n0 = (w & 3) * 32;      // 32 output cols per warp
    const bool doDn = ((w & 3) == 0);

    {  // stage the six 32KB W images once
        const int4* srcw = (const int4*)g_Wsw;
        int4* dstw = (int4*)sm;
        for (int i = t; i < 12288; i += THREADS) dstw[i] = srcw[i];
    }
    for (int i = t; i < 384; i += THREADS) fbs[i] = feat_b[i];
    __syncthreads();

    const int strb = g_is64 ? 2 : 1;
    const float gb0 = gate_b[0], gb1 = gate_b[1], gb2 = gate_b[2];
    const int lr = t >> 3, lp = t & 7;   // loader: row 0..63, 16-col part

    // fragment addressing constants
    const int arow = rg + (lane & 15);
    const uint32_t abase = (uint32_t)arow * 256;
    const int a_sw = arow & 7, a_odd = lane >> 4;
    const int brow0 = n0 + (lane & 7) + ((lane >> 4) << 3);
    const int brow1 = brow0 + 16;
    const uint32_t bbase0 = (uint32_t)brow0 * 256;
    const uint32_t bbase1 = (uint32_t)brow1 * 256;
    const int b_sw0 = brow0 & 7, b_sw1 = brow1 & 7, b_odd = (lane >> 3) & 1;

    const int g = lane >> 2, tq = lane & 3;

    // ---- prefetch tile 0
    float4 f[4];
    {
        long long crow = (long long)blockIdx.x * 64 + lr;
        if (crow >= N) crow = N - 1;
        const float4* xr = ((const float4*)x) + crow * 32;
#pragma unroll
        for (int j = 0; j < 4; j++) f[j] = __ldg(xr + lp * 4 + j);
    }

    for (int tile = blockIdx.x; tile < ntiles; tile += gridDim.x) {
        const long long row0 = (long long)tile * 64;

        // ---- convert phase: gates, bf16 split -> smem, x copy (from regs)
        {
            const long long grow = row0 + lr;
            const bool ok = grow < (long long)N;
            float p0 = 0.f, p1 = 0.f, p2 = 0.f;
#pragma unroll
            for (int j = 0; j < 4; j++) {
                float4 q0 = __ldg(((const float4*)gate_w) + lp * 4 + j);
                float4 q1 = __ldg(((const float4*)gate_w) + 32 + lp * 4 + j);
                float4 q2 = __ldg(((const float4*)gate_w) + 64 + lp * 4 + j);
                p0 += f[j].x * q0.x + f[j].y * q0.y + f[j].z * q0.z + f[j].w * q0.w;
                p1 += f[j].x * q1.x + f[j].y * q1.y + f[j].z * q1.z + f[j].w * q1.w;
                p2 += f[j].x * q2.x + f[j].y * q2.y + f[j].z * q2.z + f[j].w * q2.w;
            }
#pragma unroll
            for (int o = 4; o > 0; o >>= 1) {
                p0 += __shfl_down_sync(0xffffffffu, p0, o, 8);
                p1 += __shfl_down_sync(0xffffffffu, p1, o, 8);
                p2 += __shfl_down_sync(0xffffffffu, p2, o, 8);
            }
            if (lp == 0) {
                eS[0 * 64 + lr] = ok ? expf(p0 + gb0) : 0.f;
                eS[1 * 64 + lr] = ok ? expf(p1 + gb1) : 0.f;
                eS[2 * 64 + lr] = ok ? expf(p2 + gb2) : 0.f;
                long long crow = ok ? grow : (long long)N - 1;
                bS[lr] = bptr[crow * strb];
            }
#pragma unroll
            for (int half = 0; half < 2; half++) {
                float4 fa = f[2 * half], fb4 = f[2 * half + 1];
                __nv_bfloat162 h0 = __floats2bfloat162_rn(fa.x, fa.y);
                __nv_bfloat162 h1 = __floats2bfloat162_rn(fa.z, fa.w);
                __nv_bfloat162 h2 = __floats2bfloat162_rn(fb4.x, fb4.y);
                __nv_bfloat162 h3 = __floats2bfloat162_rn(fb4.z, fb4.w);
                float2 q0 = __bfloat1622float2(h0), q1 = __bfloat1622float2(h1);
                float2 q2 = __bfloat1622float2(h2), q3 = __bfloat1622float2(h3);
                __nv_bfloat162 l0 = __floats2bfloat162_rn(fa.x - q0.x, fa.y - q0.y);
                __nv_bfloat162 l1 = __floats2bfloat162_rn(fa.z - q1.x, fa.w - q1.y);
                __nv_bfloat162 l2 = __floats2bfloat162_rn(fb4.x - q2.x, fb4.y - q2.y);
                __nv_bfloat162 l3 = __floats2bfloat162_rn(fb4.z - q3.x, fb4.w - q3.y);
                int chunk = lp * 2 + half;
                int off = lr * 256 + ((chunk ^ (lr & 7)) << 4);
                *(uint4*)(sm + OFF_XHI + off) = make_uint4(
                    *(uint32_t*)&h0, *(uint32_t*)&h1, *(uint32_t*)&h2, *(uint32_t*)&h3);
                *(uint4*)(sm + OFF_XLO + off) = make_uint4(
                    *(uint32_t*)&l0, *(uint32_t*)&l1, *(uint32_t*)&l2, *(uint32_t*)&l3);
            }
            if (ok && x_out) {
#pragma unroll
                for (int j = 0; j < 4; j++)
                    ((float4*)x_out)[grow * 32 + lp * 4 + j] = f[j];
            }
        }
        __syncthreads();

        // ---- prefetch next tile into regs (hidden under GEMM)
        {
            long long nt = (long long)tile + gridDim.x;
            if (nt < ntiles) {
                long long crow = nt * 64 + lr;
                if (crow >= N) crow = N - 1;
                const float4* xr = ((const float4*)x) + crow * 32;
#pragma unroll
                for (int j = 0; j < 4; j++) f[j] = __ldg(xr + lp * 4 + j);
            }
        }

        // per-warp segment info
        const int segLo = bS[rg], segHi = bS[rg + 15];
        const int mybA = bS[rg + g], mybB = bS[rg + g + 8];

#pragma unroll 1
        for (int s = 0; s < 3; s++) {
            // ---- GEMM: warp = 16 rows x 32 cols, bf16x3
            float Ca[4][4], Cb[4][4];
#pragma unroll
            for (int nf = 0; nf < 4; nf++)
#pragma unroll
                for (int q = 0; q < 4; q++) { Ca[nf][q] = 0.f; Cb[nf][q] = 0.f; }
            const uint32_t whB = sb + (2 * s) * 32768;
            const uint32_t wlB = sb + (2 * s + 1) * 32768;
#pragma unroll
            for (int kb = 0; kb < 8; kb++) {
                uint32_t Ah[4], Al[4], Bh0[4], Bh1[4], Bl0[4], Bl1[4];
                uint32_t aoff = abase + (((2 * kb + a_odd) ^ a_sw) << 4);
                ldsm4(Ah, xhiB + aoff);
                ldsm4(Al, xloB + aoff);
                uint32_t boff0 = bbase0 + (((2 * kb + b_odd) ^ b_sw0) << 4);
                uint32_t boff1 = bbase1 + (((2 * kb + b_odd) ^ b_sw1) << 4);
                ldsm4(Bh0, whB + boff0);
                ldsm4(Bh1, whB + boff1);
                ldsm4(Bl0, wlB + boff0);
                ldsm4(Bl1, wlB + boff1);
#pragma unroll
                for (int nf = 0; nf < 2; nf++) {
                    mma16816(Ca[nf], Ah, Bh0[2 * nf], Bh0[2 * nf + 1]);
                    mma16816(Cb[nf], Al, Bh0[2 * nf], Bh0[2 * nf + 1]);
                    mma16816(Cb[nf], Ah, Bl0[2 * nf], Bl0[2 * nf + 1]);
                    mma16816(Ca[nf + 2], Ah, Bh1[2 * nf], Bh1[2 * nf + 1]);
                    mma16816(Cb[nf + 2], Al, Bh1[2 * nf], Bh1[2 * nf + 1]);
                    mma16816(Cb[nf + 2], Ah, Bl1[2 * nf], Bl1[2 * nf + 1]);
                }
            }

            // ---- register epilogue
            const float eA = eS[s * 64 + rg + g];
            const float eB = eS[s * 64 + rg + g + 8];
            float vA[4][2], vB[4][2];
#pragma unroll
            for (int nf = 0; nf < 4; nf++) {
                int c = n0 + nf * 8 + tq * 2;
                float bi0 = fbs[s * 128 + c], bi1 = fbs[s * 128 + c + 1];
                vA[nf][0] = leaky1(Ca[nf][0] + Cb[nf][0] + bi0) * eA;
                vA[nf][1] = leaky1(Ca[nf][1] + Cb[nf][1] + bi1) * eA;
                vB[nf][0] = leaky1(Ca[nf][2] + Cb[nf][2] + bi0) * eB;
                vB[nf][1] = leaky1(Ca[nf][3] + Cb[nf][3] + bi1) * eB;
            }
            for (int seg = segLo; seg <= segHi; ++seg) {
                bool mA = (mybA == seg), mB = (mybB == seg);
                float tv[4][2];
#pragma unroll
                for (int nf = 0; nf < 4; nf++) {
                    tv[nf][0] = (mA ? vA[nf][0] : 0.f) + (mB ? vB[nf][0] : 0.f);
                    tv[nf][1] = (mA ? vA[nf][1] : 0.f) + (mB ? vB[nf][1] : 0.f);
                }
                float te = (tq == 0) ? ((mA ? eA : 0.f) + (mB ? eB : 0.f)) : 0.f;
#pragma unroll
                for (int o = 4; o <= 16; o <<= 1) {
#pragma unroll
                    for (int nf = 0; nf < 4; nf++) {
                        tv[nf][0] += __shfl_xor_sync(0xffffffffu, tv[nf][0], o);
                        tv[nf][1] += __shfl_xor_sync(0xffffffffu, tv[nf][1], o);
                    }
                    te += __shfl_xor_sync(0xffffffffu, te, o);
                }
                if (lane < 4) {
                    float* du = &g_U[((long long)s * G + seg) * 128];
#pragma unroll
                    for (int nf = 0; nf < 4; nf++) {
                        int c = n0 + nf * 8 + tq * 2;
                        atomicAdd(du + c, tv[nf][0]);
                        atomicAdd(du + c + 1, tv[nf][1]);
                    }
                    if (doDn && lane == 0) atomicAdd(&g_Dn[s * G + seg], te);
                }
            }
        }
        __syncthreads();  // all warps done with smem x before next convert
    }
}

__global__ void __launch_bounds__(256) transform_step(
    const float* __restrict__ U, const float* __restrict__ Dn,
    const float* __restrict__ xg_in, const float* __restrict__ tw,
    const float* __restrict__ tb, float* __restrict__ xg_out, int G) {
    __shared__ float cat[32][257];
    int t = threadIdx.x;
    int g0 = blockIdx.x * 32;
    for (int i = t; i < 32 * 256; i += 256) {
        int gi = i >> 8, k = i & 255;
        int g = g0 + gi;
        float v = 0.f;
        if (g < G) {
            if (k < 128) {
                float d = Dn[g];
                v = d > 0.f ? U[(size_t)g * 128 + k] / d : 0.f;
            } else {
                v = xg_in[(size_t)g * 128 + (k - 128)];
            }
        }
        cat[gi][k] = v;
    }
    __syncthreads();
    int col = t & 127, h16 = (t >> 7) * 16;
    float acc[16];
    float bias = tb[col];
#pragma unroll
    for (int gi = 0; gi < 16; gi++) acc[gi] = bias;
#pragma unroll 2
    for (int k = 0; k < 256; k++) {
        float wv = __ldg(tw + k * 128 + col);
#pragma unroll
        for (int gi = 0; gi < 16; gi++) acc[gi] += cat[h16 + gi][k] * wv;
    }
#pragma unroll
    for (int gi = 0; gi < 16; gi++) {
        int g = g0 + h16 + gi;
        if (g < G)
            xg_out[(size_t)g * 128 + col] = leaky1(acc[gi]) + cat[h16 + gi][128 + col];
    }
}

extern "C" void kernel_launch(void* const* d_in, const int* in_sizes, int n_in,
                              void* d_out, int out_size) {
    const float* x = (const float*)d_in[0];
    const float* xg0 = (const float*)d_in[1];
    const int* bp = (const int*)d_in[4];
    const float* gate_w = (const float*)d_in[n_in - 6];
    const float* gate_b = (const float*)d_in[n_in - 5];
    const float* feat_w = (const float*)d_in[n_in - 4];
    const float* feat_b = (const float*)d_in[n_in - 3];
    const float* tr_w = (const float*)d_in[n_in - 2];
    const float* tr_b = (const float*)d_in[n_in - 1];

    int N = in_sizes[0] / 128;
    int G = in_sizes[1] / 128;

    float* out = (float*)d_out;
    float* x_out = 0;
    float* xg_final = out;
    if ((long long)out_size >= (long long)N * 128 + (long long)G * 128) {
        x_out = out;
        xg_final = out + (size_t)N * 128;
    }

    cudaFuncSetAttribute(fused_pool, cudaFuncAttributeMaxDynamicSharedMemorySize,
                         SMEM_BYTES);

    init_kernel<<<512, 256>>>(bp, feat_w, N, G);

    int nsm = 148, dev = 0;
    cudaGetDevice(&dev);
    cudaDeviceGetAttribute(&nsm, cudaDevAttrMultiProcessorCount, dev);
    int ntiles = (N + 63) / 64;
    int grid = nsm < ntiles ? nsm : ntiles;
    fused_pool<<<grid, THREADS, SMEM_BYTES>>>(x, bp, gate_w, gate_b, feat_b,
                                              x_out, N, G, ntiles);

    float *dU, *dD, *dA, *dB;
    cudaGetSymbolAddress((void**)&dU, g_U);
    cudaGetSymbolAddress((void**)&dD, g_Dn);
    cudaGetSymbolAddress((void**)&dA, g_xgA);
    cudaGetSymbolAddress((void**)&dB, g_xgB);

    int tblk = (G + 31) / 32;
    transform_step<<<tblk, 256>>>(dU, dD, xg0, tr_w, tr_b, dA, G);
    transform_step<<<tblk, 256>>>(dU + (size_t)G * 128, dD + G, dA,
                                  tr_w + 256 * 128, tr_b + 128, dB, G);
    transform_step<<<tblk, 256>>>(dU + (size_t)2 * G * 128, dD + 2 * G, dB,
                                  tr_w + 2 * 256 * 128, tr_b + 2 * 128,
                                  xg_final, G);
}

// round 9
// speedup vs baseline: 5.1433x; 1.2846x over previous
#include <cuda_runtime.h>
#include <cuda_fp16.h>
#include <cstdint>

// ---------------------------------------------------------------------------
// PoolOnlyGNN — mma.sync fp16x2 (x hi/lo split, W rounded once), persistent
// CTAs, 64-row tiles, cross-tile register prefetch, register epilogue.
// ---------------------------------------------------------------------------

#define MAXG  8192
#define THREADS 512

__device__ float g_U[3 * MAXG * 128];
__device__ float g_Dn[3 * MAXG];
__device__ int   g_is64;
__device__ unsigned short g_Wsw[3 * 16384];  // Wh (fp16) x 3 steps, ldmatrix layout
__device__ float g_xgA[MAXG * 128];
__device__ float g_xgB[MAXG * 128];

__device__ __forceinline__ uint32_t smem_u32(const void* p) {
    uint32_t a;
    asm("{ .reg .u64 t; cvta.to.shared.u64 t, %1; cvt.u32.u64 %0, t; }"
        : "=r"(a) : "l"(p));
    return a;
}
__device__ __forceinline__ void ldsm4(uint32_t* r, uint32_t a) {
    asm volatile("ldmatrix.sync.aligned.m8n8.x4.shared.b16 {%0,%1,%2,%3}, [%4];"
                 : "=r"(r[0]), "=r"(r[1]), "=r"(r[2]), "=r"(r[3]) : "r"(a));
}
__device__ __forceinline__ void mma16816(float* c, const uint32_t* a,
                                         uint32_t b0, uint32_t b1) {
    asm volatile(
        "mma.sync.aligned.m16n8k16.row.col.f32.f16.f16.f32 "
        "{%0,%1,%2,%3}, {%4,%5,%6,%7}, {%8,%9}, {%0,%1,%2,%3};"
        : "+f"(c[0]), "+f"(c[1]), "+f"(c[2]), "+f"(c[3])
        : "r"(a[0]), "r"(a[1]), "r"(a[2]), "r"(a[3]), "r"(b0), "r"(b1));
}
__device__ __forceinline__ float leaky1(float v) { return v >= 0.f ? v : 0.01f * v; }

// element (row n, col k) byte offset in a 128x128 fp16 ldmatrix image:
// 256B per row, 16B chunks xor-swizzled by row&7.
__device__ __forceinline__ int img_off(int n, int k) {
    return n * 256 + (((k >> 3) ^ (n & 7)) << 4) + (k & 7) * 2;
}

__global__ void init_kernel(const int* __restrict__ bptr,
                            const float* __restrict__ feat_w, int N, int G) {
    int tid = blockIdx.x * blockDim.x + threadIdx.x;
    int stride = gridDim.x * blockDim.x;
    for (int i = tid; i < 3 * G * 128; i += stride) g_U[i] = 0.f;
    for (int i = tid; i < 3 * G; i += stride) g_Dn[i] = 0.f;
    for (int i = tid; i < 3 * 16384; i += stride) {
        int s = i >> 14, r = i & 16383;
        int k = r >> 7, n = r & 127;           // feat_w[s][k][n]
        __half bh = __float2half_rn(feat_w[i]);
        int off = img_off(n, k) >> 1;
        g_Wsw[s * 16384 + off] = *(const unsigned short*)&bh;
    }
    if (tid == 0) {
        int probe = (N & 1) ? (N - 2) : (N - 1);
        if (probe < 0) probe = 0;
        g_is64 = (bptr[probe] == 0) ? 1 : 0;
    }
}

// smem byte offsets
#define OFF_W     0        // 98304  : 3 Wh images
#define OFF_XHI   98304    // 16384  : x hi (64 rows x 256B)
#define OFF_XLO   114688   // 16384
#define OFF_ES    131072   // 768    : e[3][64]
#define OFF_BS    131840   // 256    : batch id per row
#define OFF_FB    132096   // 1536   : feat_b
#define SMEM_BYTES 133632

__global__ void __launch_bounds__(THREADS, 1) fused_pool(
    const float* __restrict__ x, const int* __restrict__ bptr,
    const float* __restrict__ gate_w, const float* __restrict__ gate_b,
    const float* __restrict__ feat_b, float* __restrict__ x_out,
    int N, int G, int ntiles) {
    extern __shared__ char sm[];
    float* eS = (float*)(sm + OFF_ES);
    int* bS = (int*)(sm + OFF_BS);
    float* fbs = (float*)(sm + OFF_FB);
    const uint32_t sb = smem_u32(sm);
    const uint32_t xhiB = sb + OFF_XHI, xloB = sb + OFF_XLO;

    const int t = threadIdx.x, lane = t & 31, w = t >> 5;
    const int rg = (w >> 2) * 16;     // row-group base (4 groups of 16 rows)
    const int n0 = (w & 3) * 32;      // 32 output cols per warp
    const bool doDn = ((w & 3) == 0);

    {  // stage the three 32KB Wh images once
        const int4* srcw = (const int4*)g_Wsw;
        int4* dstw = (int4*)sm;
        for (int i = t; i < 6144; i += THREADS) dstw[i] = srcw[i];
    }
    for (int i = t; i < 384; i += THREADS) fbs[i] = feat_b[i];
    __syncthreads();

    const int strb = g_is64 ? 2 : 1;
    const float gb0 = gate_b[0], gb1 = gate_b[1], gb2 = gate_b[2];
    const int lr = t >> 3, lp = t & 7;   // loader: row 0..63, 16-col part

    // fragment addressing constants
    const int arow = rg + (lane & 15);
    const uint32_t abase = (uint32_t)arow * 256;
    const int a_sw = arow & 7, a_odd = lane >> 4;
    const int brow0 = n0 + (lane & 7) + ((lane >> 4) << 3);
    const int brow1 = brow0 + 16;
    const uint32_t bbase0 = (uint32_t)brow0 * 256;
    const uint32_t bbase1 = (uint32_t)brow1 * 256;
    const int b_sw0 = brow0 & 7, b_sw1 = brow1 & 7, b_odd = (lane >> 3) & 1;

    const int g = lane >> 2, tq = lane & 3;

    // ---- prefetch tile 0
    float4 f[4];
    {
        long long crow = (long long)blockIdx.x * 64 + lr;
        if (crow >= N) crow = N - 1;
        const float4* xr = ((const float4*)x) + crow * 32;
#pragma unroll
        for (int j = 0; j < 4; j++) f[j] = __ldg(xr + lp * 4 + j);
    }

    for (int tile = blockIdx.x; tile < ntiles; tile += gridDim.x) {
        const long long row0 = (long long)tile * 64;

        // ---- convert phase: gates, fp16 split -> smem, x copy (from regs)
        {
            const long long grow = row0 + lr;
            const bool ok = grow < (long long)N;
            float p0 = 0.f, p1 = 0.f, p2 = 0.f;
#pragma unroll
            for (int j = 0; j < 4; j++) {
                float4 q0 = __ldg(((const float4*)gate_w) + lp * 4 + j);
                float4 q1 = __ldg(((const float4*)gate_w) + 32 + lp * 4 + j);
                float4 q2 = __ldg(((const float4*)gate_w) + 64 + lp * 4 + j);
                p0 += f[j].x * q0.x + f[j].y * q0.y + f[j].z * q0.z + f[j].w * q0.w;
                p1 += f[j].x * q1.x + f[j].y * q1.y + f[j].z * q1.z + f[j].w * q1.w;
                p2 += f[j].x * q2.x + f[j].y * q2.y + f[j].z * q2.z + f[j].w * q2.w;
            }
#pragma unroll
            for (int o = 4; o > 0; o >>= 1) {
                p0 += __shfl_down_sync(0xffffffffu, p0, o, 8);
                p1 += __shfl_down_sync(0xffffffffu, p1, o, 8);
                p2 += __shfl_down_sync(0xffffffffu, p2, o, 8);
            }
            if (lp == 0) {
                eS[0 * 64 + lr] = ok ? expf(p0 + gb0) : 0.f;
                eS[1 * 64 + lr] = ok ? expf(p1 + gb1) : 0.f;
                eS[2 * 64 + lr] = ok ? expf(p2 + gb2) : 0.f;
                long long crow = ok ? grow : (long long)N - 1;
                bS[lr] = bptr[crow * strb];
            }
#pragma unroll
            for (int half = 0; half < 2; half++) {
                float4 fa = f[2 * half], fb4 = f[2 * half + 1];
                __half2 h0 = __floats2half2_rn(fa.x, fa.y);
                __half2 h1 = __floats2half2_rn(fa.z, fa.w);
                __half2 h2 = __floats2half2_rn(fb4.x, fb4.y);
                __half2 h3 = __floats2half2_rn(fb4.z, fb4.w);
                float2 q0 = __half22float2(h0), q1 = __half22float2(h1);
                float2 q2 = __half22float2(h2), q3 = __half22float2(h3);
                __half2 l0 = __floats2half2_rn(fa.x - q0.x, fa.y - q0.y);
                __half2 l1 = __floats2half2_rn(fa.z - q1.x, fa.w - q1.y);
                __half2 l2 = __floats2half2_rn(fb4.x - q2.x, fb4.y - q2.y);
                __half2 l3 = __floats2half2_rn(fb4.z - q3.x, fb4.w - q3.y);
                int chunk = lp * 2 + half;
                int off = lr * 256 + ((chunk ^ (lr & 7)) << 4);
                *(uint4*)(sm + OFF_XHI + off) = make_uint4(
                    *(uint32_t*)&h0, *(uint32_t*)&h1, *(uint32_t*)&h2, *(uint32_t*)&h3);
                *(uint4*)(sm + OFF_XLO + off) = make_uint4(
                    *(uint32_t*)&l0, *(uint32_t*)&l1, *(uint32_t*)&l2, *(uint32_t*)&l3);
            }
            if (ok && x_out) {
#pragma unroll
                for (int j = 0; j < 4; j++)
                    ((float4*)x_out)[grow * 32 + lp * 4 + j] = f[j];
            }
        }
        __syncthreads();

        // ---- prefetch next tile into regs (hidden under GEMM)
        {
            long long nt = (long long)tile + gridDim.x;
            if (nt < ntiles) {
                long long crow = nt * 64 + lr;
                if (crow >= N) crow = N - 1;
                const float4* xr = ((const float4*)x) + crow * 32;
#pragma unroll
                for (int j = 0; j < 4; j++) f[j] = __ldg(xr + lp * 4 + j);
            }
        }

        // per-warp segment info
        const int segLo = bS[rg], segHi = bS[rg + 15];
        const int mybA = bS[rg + g], mybB = bS[rg + g + 8];

#pragma unroll 1
        for (int s = 0; s < 3; s++) {
            // ---- GEMM: warp = 16 rows x 32 cols, fp16x2 (xh + xl, Wh)
            float Ca[4][4], Cb[4][4];
#pragma unroll
            for (int nf = 0; nf < 4; nf++)
#pragma unroll
                for (int q = 0; q < 4; q++) { Ca[nf][q] = 0.f; Cb[nf][q] = 0.f; }
            const uint32_t whB = sb + s * 32768;
#pragma unroll
            for (int kb = 0; kb < 8; kb++) {
                uint32_t Ah[4], Al[4], Bh0[4], Bh1[4];
                uint32_t aoff = abase + (((2 * kb + a_odd) ^ a_sw) << 4);
                ldsm4(Ah, xhiB + aoff);
                ldsm4(Al, xloB + aoff);
                uint32_t boff0 = bbase0 + (((2 * kb + b_odd) ^ b_sw0) << 4);
                uint32_t boff1 = bbase1 + (((2 * kb + b_odd) ^ b_sw1) << 4);
                ldsm4(Bh0, whB + boff0);
                ldsm4(Bh1, whB + boff1);
#pragma unroll
                for (int nf = 0; nf < 2; nf++) {
                    mma16816(Ca[nf], Ah, Bh0[2 * nf], Bh0[2 * nf + 1]);
                    mma16816(Cb[nf], Al, Bh0[2 * nf], Bh0[2 * nf + 1]);
                    mma16816(Ca[nf + 2], Ah, Bh1[2 * nf], Bh1[2 * nf + 1]);
                    mma16816(Cb[nf + 2], Al, Bh1[2 * nf], Bh1[2 * nf + 1]);
                }
            }

            // ---- register epilogue
            const float eA = eS[s * 64 + rg + g];
            const float eB = eS[s * 64 + rg + g + 8];
            float vA[4][2], vB[4][2];
#pragma unroll
            for (int nf = 0; nf < 4; nf++) {
                int c = n0 + nf * 8 + tq * 2;
                float bi0 = fbs[s * 128 + c], bi1 = fbs[s * 128 + c + 1];
                vA[nf][0] = leaky1(Ca[nf][0] + Cb[nf][0] + bi0) * eA;
                vA[nf][1] = leaky1(Ca[nf][1] + Cb[nf][1] + bi1) * eA;
                vB[nf][0] = leaky1(Ca[nf][2] + Cb[nf][2] + bi0) * eB;
                vB[nf][1] = leaky1(Ca[nf][3] + Cb[nf][3] + bi1) * eB;
            }
            for (int seg = segLo; seg <= segHi; ++seg) {
                bool mA = (mybA == seg), mB = (mybB == seg);
                float tv[4][2];
#pragma unroll
                for (int nf = 0; nf < 4; nf++) {
                    tv[nf][0] = (mA ? vA[nf][0] : 0.f) + (mB ? vB[nf][0] : 0.f);
                    tv[nf][1] = (mA ? vA[nf][1] : 0.f) + (mB ? vB[nf][1] : 0.f);
                }
                float te = (tq == 0) ? ((mA ? eA : 0.f) + (mB ? eB : 0.f)) : 0.f;
#pragma unroll
                for (int o = 4; o <= 16; o <<= 1) {
#pragma unroll
                    for (int nf = 0; nf < 4; nf++) {
                        tv[nf][0] += __shfl_xor_sync(0xffffffffu, tv[nf][0], o);
                        tv[nf][1] += __shfl_xor_sync(0xffffffffu, tv[nf][1], o);
                    }
                    te += __shfl_xor_sync(0xffffffffu, te, o);
                }
                if (lane < 4) {
                    float* du = &g_U[((long long)s * G + seg) * 128];
#pragma unroll
                    for (int nf = 0; nf < 4; nf++) {
                        int c = n0 + nf * 8 + tq * 2;
                        atomicAdd(du + c, tv[nf][0]);
                        atomicAdd(du + c + 1, tv[nf][1]);
                    }
                    if (doDn && lane == 0) atomicAdd(&g_Dn[s * G + seg], te);
                }
            }
        }
        __syncthreads();  // all warps done with smem x before next convert
    }
}

__global__ void __launch_bounds__(256) transform_step(
    const float* __restrict__ U, const float* __restrict__ Dn,
    const float* __restrict__ xg_in, const float* __restrict__ tw,
    const float* __restrict__ tb, float* __restrict__ xg_out, int G) {
    __shared__ float cat[16][257];
    int t = threadIdx.x;
    int g0 = blockIdx.x * 16;
    for (int i = t; i < 16 * 256; i += 256) {
        int gi = i >> 8, k = i & 255;
        int g = g0 + gi;
        float v = 0.f;
        if (g < G) {
            if (k < 128) {
                float d = Dn[g];
                v = d > 0.f ? U[(size_t)g * 128 + k] / d : 0.f;
            } else {
                v = xg_in[(size_t)g * 128 + (k - 128)];
            }
        }
        cat[gi][k] = v;
    }
    __syncthreads();
    int col = t & 127, h8 = (t >> 7) * 8;
    float acc[8];
    float bias = tb[col];
#pragma unroll
    for (int gi = 0; gi < 8; gi++) acc[gi] = bias;
#pragma unroll 4
    for (int k = 0; k < 256; k++) {
        float wv = __ldg(tw + k * 128 + col);
#pragma unroll
        for (int gi = 0; gi < 8; gi++) acc[gi] += cat[h8 + gi][k] * wv;
    }
#pragma unroll
    for (int gi = 0; gi < 8; gi++) {
        int g = g0 + h8 + gi;
        if (g < G)
            xg_out[(size_t)g * 128 + col] = leaky1(acc[gi]) + cat[h8 + gi][128 + col];
    }
}

extern "C" void kernel_launch(void* const* d_in, const int* in_sizes, int n_in,
                              void* d_out, int out_size) {
    const float* x = (const float*)d_in[0];
    const float* xg0 = (const float*)d_in[1];
    const int* bp = (const int*)d_in[4];
    const float* gate_w = (const float*)d_in[n_in - 6];
    const float* gate_b = (const float*)d_in[n_in - 5];
    const float* feat_w = (const float*)d_in[n_in - 4];
    const float* feat_b = (const float*)d_in[n_in - 3];
    const float* tr_w = (const float*)d_in[n_in - 2];
    const float* tr_b = (const float*)d_in[n_in - 1];

    int N = in_sizes[0] / 128;
    int G = in_sizes[1] / 128;

    float* out = (float*)d_out;
    float* x_out = 0;
    float* xg_final = out;
    if ((long long)out_size >= (long long)N * 128 + (long long)G * 128) {
        x_out = out;
        xg_final = out + (size_t)N * 128;
    }

    cudaFuncSetAttribute(fused_pool, cudaFuncAttributeMaxDynamicSharedMemorySize,
                         SMEM_BYTES);

    init_kernel<<<512, 256>>>(bp, feat_w, N, G);

    int nsm = 148, dev = 0;
    cudaGetDevice(&dev);
    cudaDeviceGetAttribute(&nsm, cudaDevAttrMultiProcessorCount, dev);
    int ntiles = (N + 63) / 64;
    int grid = nsm < ntiles ? nsm : ntiles;
    fused_pool<<<grid, THREADS, SMEM_BYTES>>>(x, bp, gate_w, gate_b, feat_b,
                                              x_out, N, G, ntiles);

    float *dU, *dD, *dA, *dB;
    cudaGetSymbolAddress((void**)&dU, g_U);
    cudaGetSymbolAddress((void**)&dD, g_Dn);
    cudaGetSymbolAddress((void**)&dA, g_xgA);
    cudaGetSymbolAddress((void**)&dB, g_xgB);

    int tblk = (G + 15) / 16;
    transform_step<<<tblk, 256>>>(dU, dD, xg0, tr_w, tr_b, dA, G);
    transform_step<<<tblk, 256>>>(dU + (size_t)G * 128, dD + G, dA,
                                  tr_w + 256 * 128, tr_b + 128, dB, G);
    transform_step<<<tblk, 256>>>(dU + (size_t)2 * G * 128, dD + 2 * G, dB,
                                  tr_w + 2 * 256 * 128, tr_b + 2 * 128,
                                  xg_final, G);
}

// round 10
// speedup vs baseline: 5.7241x; 1.1129x over previous
#include <cuda_runtime.h>
#include <cuda_fp16.h>
#include <cstdint>

// ---------------------------------------------------------------------------
// PoolOnlyGNN — mma.sync single-fp16 GEMM (x and W rounded once), persistent
// CTAs, 64-row tiles, cross-tile register prefetch, register epilogue.
// ---------------------------------------------------------------------------

#define MAXG  8192
#define THREADS 512

__device__ float g_U[3 * MAXG * 128];
__device__ float g_Dn[3 * MAXG];
__device__ int   g_is64;
__device__ unsigned short g_Wsw[3 * 16384];  // Wh (fp16) x 3 steps, ldmatrix layout
__device__ float g_xgA[MAXG * 128];
__device__ float g_xgB[MAXG * 128];

__device__ __forceinline__ uint32_t smem_u32(const void* p) {
    uint32_t a;
    asm("{ .reg .u64 t; cvta.to.shared.u64 t, %1; cvt.u32.u64 %0, t; }"
        : "=r"(a) : "l"(p));
    return a;
}
__device__ __forceinline__ void ldsm4(uint32_t* r, uint32_t a) {
    asm volatile("ldmatrix.sync.aligned.m8n8.x4.shared.b16 {%0,%1,%2,%3}, [%4];"
                 : "=r"(r[0]), "=r"(r[1]), "=r"(r[2]), "=r"(r[3]) : "r"(a));
}
__device__ __forceinline__ void mma16816(float* c, const uint32_t* a,
                                         uint32_t b0, uint32_t b1) {
    asm volatile(
        "mma.sync.aligned.m16n8k16.row.col.f32.f16.f16.f32 "
        "{%0,%1,%2,%3}, {%4,%5,%6,%7}, {%8,%9}, {%0,%1,%2,%3};"
        : "+f"(c[0]), "+f"(c[1]), "+f"(c[2]), "+f"(c[3])
        : "r"(a[0]), "r"(a[1]), "r"(a[2]), "r"(a[3]), "r"(b0), "r"(b1));
}
__device__ __forceinline__ float leaky1(float v) { return v >= 0.f ? v : 0.01f * v; }

// element (row n, col k) byte offset in a 128x128 fp16 ldmatrix image:
// 256B per row, 16B chunks xor-swizzled by row&7.
__device__ __forceinline__ int img_off(int n, int k) {
    return n * 256 + (((k >> 3) ^ (n & 7)) << 4) + (k & 7) * 2;
}

__global__ void init_kernel(const int* __restrict__ bptr,
                            const float* __restrict__ feat_w, int N, int G) {
    int tid = blockIdx.x * blockDim.x + threadIdx.x;
    int stride = gridDim.x * blockDim.x;
    for (int i = tid; i < 3 * G * 128; i += stride) g_U[i] = 0.f;
    for (int i = tid; i < 3 * G; i += stride) g_Dn[i] = 0.f;
    for (int i = tid; i < 3 * 16384; i += stride) {
        int s = i >> 14, r = i & 16383;
        int k = r >> 7, n = r & 127;           // feat_w[s][k][n]
        __half bh = __float2half_rn(feat_w[i]);
        int off = img_off(n, k) >> 1;
        g_Wsw[s * 16384 + off] = *(const unsigned short*)&bh;
    }
    if (tid == 0) {
        int probe = (N & 1) ? (N - 2) : (N - 1);
        if (probe < 0) probe = 0;
        g_is64 = (bptr[probe] == 0) ? 1 : 0;
    }
}

// smem byte offsets
#define OFF_W     0        // 98304  : 3 Wh images
#define OFF_XHI   98304    // 16384  : x fp16 (64 rows x 256B)
#define OFF_ES    114688   // 768    : e[3][64]
#define OFF_BS    115456   // 256    : batch id per row
#define OFF_FB    115712   // 1536   : feat_b
#define SMEM_BYTES 117248

__global__ void __launch_bounds__(THREADS, 1) fused_pool(
    const float* __restrict__ x, const int* __restrict__ bptr,
    const float* __restrict__ gate_w, const float* __restrict__ gate_b,
    const float* __restrict__ feat_b, float* __restrict__ x_out,
    int N, int G, int ntiles) {
    extern __shared__ char sm[];
    float* eS = (float*)(sm + OFF_ES);
    int* bS = (int*)(sm + OFF_BS);
    float* fbs = (float*)(sm + OFF_FB);
    const uint32_t sb = smem_u32(sm);
    const uint32_t xhiB = sb + OFF_XHI;

    const int t = threadIdx.x, lane = t & 31, w = t >> 5;
    const int rg = (w >> 2) * 16;     // row-group base (4 groups of 16 rows)
    const int n0 = (w & 3) * 32;      // 32 output cols per warp
    const bool doDn = ((w & 3) == 0);

    {  // stage the three 32KB Wh images once
        const int4* srcw = (const int4*)g_Wsw;
        int4* dstw = (int4*)sm;
        for (int i = t; i < 6144; i += THREADS) dstw[i] = srcw[i];
    }
    for (int i = t; i < 384; i += THREADS) fbs[i] = feat_b[i];
    __syncthreads();

    const int strb = g_is64 ? 2 : 1;
    const float gb0 = gate_b[0], gb1 = gate_b[1], gb2 = gate_b[2];
    const int lr = t >> 3, lp = t & 7;   // loader: row 0..63, 16-col part

    // fragment addressing constants
    const int arow = rg + (lane & 15);
    const uint32_t abase = (uint32_t)arow * 256;
    const int a_sw = arow & 7, a_odd = lane >> 4;
    const int brow0 = n0 + (lane & 7) + ((lane >> 4) << 3);
    const int brow1 = brow0 + 16;
    const uint32_t bbase0 = (uint32_t)brow0 * 256;
    const uint32_t bbase1 = (uint32_t)brow1 * 256;
    const int b_sw0 = brow0 & 7, b_sw1 = brow1 & 7, b_odd = (lane >> 3) & 1;

    const int g = lane >> 2, tq = lane & 3;

    // ---- prefetch tile 0
    float4 f[4];
    {
        long long crow = (long long)blockIdx.x * 64 + lr;
        if (crow >= N) crow = N - 1;
        const float4* xr = ((const float4*)x) + crow * 32;
#pragma unroll
        for (int j = 0; j < 4; j++) f[j] = __ldg(xr + lp * 4 + j);
    }

    for (int tile = blockIdx.x; tile < ntiles; tile += gridDim.x) {
        const long long row0 = (long long)tile * 64;

        // ---- convert phase: gates, fp16 round -> smem, x copy (from regs)
        {
            const long long grow = row0 + lr;
            const bool ok = grow < (long long)N;
            float p0 = 0.f, p1 = 0.f, p2 = 0.f;
#pragma unroll
            for (int j = 0; j < 4; j++) {
                float4 q0 = __ldg(((const float4*)gate_w) + lp * 4 + j);
                float4 q1 = __ldg(((const float4*)gate_w) + 32 + lp * 4 + j);
                float4 q2 = __ldg(((const float4*)gate_w) + 64 + lp * 4 + j);
                p0 += f[j].x * q0.x + f[j].y * q0.y + f[j].z * q0.z + f[j].w * q0.w;
                p1 += f[j].x * q1.x + f[j].y * q1.y + f[j].z * q1.z + f[j].w * q1.w;
                p2 += f[j].x * q2.x + f[j].y * q2.y + f[j].z * q2.z + f[j].w * q2.w;
            }
#pragma unroll
            for (int o = 4; o > 0; o >>= 1) {
                p0 += __shfl_down_sync(0xffffffffu, p0, o, 8);
                p1 += __shfl_down_sync(0xffffffffu, p1, o, 8);
                p2 += __shfl_down_sync(0xffffffffu, p2, o, 8);
            }
            if (lp == 0) {
                eS[0 * 64 + lr] = ok ? expf(p0 + gb0) : 0.f;
                eS[1 * 64 + lr] = ok ? expf(p1 + gb1) : 0.f;
                eS[2 * 64 + lr] = ok ? expf(p2 + gb2) : 0.f;
                long long crow = ok ? grow : (long long)N - 1;
                bS[lr] = bptr[crow * strb];
            }
#pragma unroll
            for (int half = 0; half < 2; half++) {
                float4 fa = f[2 * half], fb4 = f[2 * half + 1];
                __half2 h0 = __floats2half2_rn(fa.x, fa.y);
                __half2 h1 = __floats2half2_rn(fa.z, fa.w);
                __half2 h2 = __floats2half2_rn(fb4.x, fb4.y);
                __half2 h3 = __floats2half2_rn(fb4.z, fb4.w);
                int chunk = lp * 2 + half;
                int off = lr * 256 + ((chunk ^ (lr & 7)) << 4);
                *(uint4*)(sm + OFF_XHI + off) = make_uint4(
                    *(uint32_t*)&h0, *(uint32_t*)&h1, *(uint32_t*)&h2, *(uint32_t*)&h3);
            }
            if (ok && x_out) {
#pragma unroll
                for (int j = 0; j < 4; j++)
                    ((float4*)x_out)[grow * 32 + lp * 4 + j] = f[j];
            }
        }
        __syncthreads();

        // ---- prefetch next tile into regs (hidden under GEMM)
        {
            long long nt = (long long)tile + gridDim.x;
            if (nt < ntiles) {
                long long crow = nt * 64 + lr;
                if (crow >= N) crow = N - 1;
                const float4* xr = ((const float4*)x) + crow * 32;
#pragma unroll
                for (int j = 0; j < 4; j++) f[j] = __ldg(xr + lp * 4 + j);
            }
        }

        // per-warp segment info
        const int segLo = bS[rg], segHi = bS[rg + 15];
        const int mybA = bS[rg + g], mybB = bS[rg + g + 8];

#pragma unroll 1
        for (int s = 0; s < 3; s++) {
            // ---- GEMM: warp = 16 rows x 32 cols, single fp16
            float Ca[4][4];
#pragma unroll
            for (int nf = 0; nf < 4; nf++)
#pragma unroll
                for (int q = 0; q < 4; q++) Ca[nf][q] = 0.f;
            const uint32_t whB = sb + s * 32768;
#pragma unroll
            for (int kb = 0; kb < 8; kb++) {
                uint32_t Ah[4], Bh0[4], Bh1[4];
                uint32_t aoff = abase + (((2 * kb + a_odd) ^ a_sw) << 4);
                ldsm4(Ah, xhiB + aoff);
                uint32_t boff0 = bbase0 + (((2 * kb + b_odd) ^ b_sw0) << 4);
                uint32_t boff1 = bbase1 + (((2 * kb + b_odd) ^ b_sw1) << 4);
                ldsm4(Bh0, whB + boff0);
                ldsm4(Bh1, whB + boff1);
#pragma unroll
                for (int nf = 0; nf < 2; nf++) {
                    mma16816(Ca[nf], Ah, Bh0[2 * nf], Bh0[2 * nf + 1]);
                    mma16816(Ca[nf + 2], Ah, Bh1[2 * nf], Bh1[2 * nf + 1]);
                }
            }

            // ---- register epilogue
            const float eA = eS[s * 64 + rg + g];
            const float eB = eS[s * 64 + rg + g + 8];
            float vA[4][2], vB[4][2];
#pragma unroll
            for (int nf = 0; nf < 4; nf++) {
                int c = n0 + nf * 8 + tq * 2;
                float bi0 = fbs[s * 128 + c], bi1 = fbs[s * 128 + c + 1];
                vA[nf][0] = leaky1(Ca[nf][0] + bi0) * eA;
                vA[nf][1] = leaky1(Ca[nf][1] + bi1) * eA;
                vB[nf][0] = leaky1(Ca[nf][2] + bi0) * eB;
                vB[nf][1] = leaky1(Ca[nf][3] + bi1) * eB;
            }
            for (int seg = segLo; seg <= segHi; ++seg) {
                bool mA = (mybA == seg), mB = (mybB == seg);
                float tv[4][2];
#pragma unroll
                for (int nf = 0; nf < 4; nf++) {
                    tv[nf][0] = (mA ? vA[nf][0] : 0.f) + (mB ? vB[nf][0] : 0.f);
                    tv[nf][1] = (mA ? vA[nf][1] : 0.f) + (mB ? vB[nf][1] : 0.f);
                }
                float te = (tq == 0) ? ((mA ? eA : 0.f) + (mB ? eB : 0.f)) : 0.f;
#pragma unroll
                for (int o = 4; o <= 16; o <<= 1) {
#pragma unroll
                    for (int nf = 0; nf < 4; nf++) {
                        tv[nf][0] += __shfl_xor_sync(0xffffffffu, tv[nf][0], o);
                        tv[nf][1] += __shfl_xor_sync(0xffffffffu, tv[nf][1], o);
                    }
                    te += __shfl_xor_sync(0xffffffffu, te, o);
                }
                if (lane < 4) {
                    float* du = &g_U[((long long)s * G + seg) * 128];
#pragma unroll
                    for (int nf = 0; nf < 4; nf++) {
                        int c = n0 + nf * 8 + tq * 2;
                        atomicAdd(du + c, tv[nf][0]);
                        atomicAdd(du + c + 1, tv[nf][1]);
                    }
                    if (doDn && lane == 0) atomicAdd(&g_Dn[s * G + seg], te);
                }
            }
        }
        __syncthreads();  // all warps done with smem x before next convert
    }
}

__global__ void __launch_bounds__(256) transform_step(
    const float* __restrict__ U, const float* __restrict__ Dn,
    const float* __restrict__ xg_in, const float* __restrict__ tw,
    const float* __restrict__ tb, float* __restrict__ xg_out, int G) {
    __shared__ float cat[16][257];
    int t = threadIdx.x;
    int g0 = blockIdx.x * 16;
    for (int i = t; i < 16 * 256; i += 256) {
        int gi = i >> 8, k = i & 255;
        int g = g0 + gi;
        float v = 0.f;
        if (g < G) {
            if (k < 128) {
                float d = Dn[g];
                v = d > 0.f ? U[(size_t)g * 128 + k] / d : 0.f;
            } else {
                v = xg_in[(size_t)g * 128 + (k - 128)];
            }
        }
        cat[gi][k] = v;
    }
    __syncthreads();
    int col = t & 127, h8 = (t >> 7) * 8;
    float acc[8];
    float bias = tb[col];
#pragma unroll
    for (int gi = 0; gi < 8; gi++) acc[gi] = bias;
#pragma unroll 4
    for (int k = 0; k < 256; k++) {
        float wv = __ldg(tw + k * 128 + col);
#pragma unroll
        for (int gi = 0; gi < 8; gi++) acc[gi] += cat[h8 + gi][k] * wv;
    }
#pragma unroll
    for (int gi = 0; gi < 8; gi++) {
        int g = g0 + h8 + gi;
        if (g < G)
            xg_out[(size_t)g * 128 + col] = leaky1(acc[gi]) + cat[h8 + gi][128 + col];
    }
}

extern "C" void kernel_launch(void* const* d_in, const int* in_sizes, int n_in,
                              void* d_out, int out_size) {
    const float* x = (const float*)d_in[0];
    const float* xg0 = (const float*)d_in[1];
    const int* bp = (const int*)d_in[4];
    const float* gate_w = (const float*)d_in[n_in - 6];
    const float* gate_b = (const float*)d_in[n_in - 5];
    const float* feat_w = (const float*)d_in[n_in - 4];
    const float* feat_b = (const float*)d_in[n_in - 3];
    const float* tr_w = (const float*)d_in[n_in - 2];
    const float* tr_b = (const float*)d_in[n_in - 1];

    int N = in_sizes[0] / 128;
    int G = in_sizes[1] / 128;

    float* out = (float*)d_out;
    float* x_out = 0;
    float* xg_final = out;
    if ((long long)out_size >= (long long)N * 128 + (long long)G * 128) {
        x_out = out;
        xg_final = out + (size_t)N * 128;
    }

    cudaFuncSetAttribute(fused_pool, cudaFuncAttributeMaxDynamicSharedMemorySize,
                         SMEM_BYTES);

    init_kernel<<<512, 256>>>(bp, feat_w, N, G);

    int nsm = 148, dev = 0;
    cudaGetDevice(&dev);
    cudaDeviceGetAttribute(&nsm, cudaDevAttrMultiProcessorCount, dev);
    int ntiles = (N + 63) / 64;
    int grid = nsm < ntiles ? nsm : ntiles;
    fused_pool<<<grid, THREADS, SMEM_BYTES>>>(x, bp, gate_w, gate_b, feat_b,
                                              x_out, N, G, ntiles);

    float *dU, *dD, *dA, *dB;
    cudaGetSymbolAddress((void**)&dU, g_U);
    cudaGetSymbolAddress((void**)&dD, g_Dn);
    cudaGetSymbolAddress((void**)&dA, g_xgA);
    cudaGetSymbolAddress((void**)&dB, g_xgB);

    int tblk = (G + 15) / 16;
    transform_step<<<tblk, 256>>>(dU, dD, xg0, tr_w, tr_b, dA, G);
    transform_step<<<tblk, 256>>>(dU + (size_t)G * 128, dD + G, dA,
                                  tr_w + 256 * 128, tr_b + 128, dB, G);
    transform_step<<<tblk, 256>>>(dU + (size_t)2 * G * 128, dD + 2 * G, dB,
                                  tr_w + 2 * 256 * 128, tr_b + 2 * 128,
                                  xg_final, G);
}